// round 3
// baseline (speedup 1.0000x reference)
#include <cuda_runtime.h>
#include <math.h>

#define D_MODEL 1024
#define F_FFN   4096
#define B_SZ    4
#define S_LEN   2048
#define N_HEADS 16
#define DK      64
#define M_ROWS  (B_SZ * S_LEN)   // 8192
#define LN_EPS  1e-6f

// ---------------- scratch (no allocs allowed) ----------------
__device__ float g_xn [(size_t)M_ROWS * D_MODEL];
__device__ float g_q  [(size_t)M_ROWS * D_MODEL];
__device__ float g_k  [(size_t)M_ROWS * D_MODEL];
__device__ float g_v  [(size_t)M_ROWS * D_MODEL];
__device__ float g_ctx[(size_t)M_ROWS * D_MODEL];
__device__ float g_h  [(size_t)M_ROWS * D_MODEL];
__device__ float g_xn2[(size_t)M_ROWS * D_MODEL];
__device__ float g_mid[(size_t)M_ROWS * F_FFN];

// ---------------- LayerNorm (torch semantics: ddof=1, eps added to std) ----
__global__ void __launch_bounds__(256) ln_kernel(
    const float* __restrict__ x,
    const float* __restrict__ alpha,
    const float* __restrict__ beta,
    float* __restrict__ out)
{
    __shared__ float red[32];
    const int row = blockIdx.x;
    const int tid = threadIdx.x;

    const float4 v = ((const float4*)(x + (size_t)row * D_MODEL))[tid];
    float s  = v.x + v.y + v.z + v.w;
    float s2 = v.x * v.x + v.y * v.y + v.z * v.z + v.w * v.w;
    #pragma unroll
    for (int off = 16; off > 0; off >>= 1) {
        s  += __shfl_xor_sync(0xffffffffu, s,  off);
        s2 += __shfl_xor_sync(0xffffffffu, s2, off);
    }
    const int warp = tid >> 5;
    if ((tid & 31) == 0) { red[warp] = s; red[8 + warp] = s2; }
    __syncthreads();
    if (tid == 0) {
        float ts = 0.f, ts2 = 0.f;
        #pragma unroll
        for (int i = 0; i < 8; i++) { ts += red[i]; ts2 += red[8 + i]; }
        const float mean = ts * (1.0f / (float)D_MODEL);
        float var = (ts2 - (float)D_MODEL * mean * mean) * (1.0f / (float)(D_MODEL - 1));
        var = fmaxf(var, 0.0f);
        red[16] = mean;
        red[17] = 1.0f / (sqrtf(var) + LN_EPS);
    }
    __syncthreads();
    const float mean = red[16], inv = red[17];
    const float4 a = ((const float4*)alpha)[tid];
    const float4 b = ((const float4*)beta)[tid];
    float4 o;
    o.x = a.x * (v.x - mean) * inv + b.x;
    o.y = a.y * (v.y - mean) * inv + b.y;
    o.z = a.z * (v.z - mean) * inv + b.z;
    o.w = a.w * (v.w - mean) * inv + b.w;
    ((float4*)(out + (size_t)row * D_MODEL))[tid] = o;
}

// ---------------- SGEMM: C[M,N] = op(A[M,K] @ B[K,N] + bias [+ res]) --------
// 128x128 block tile, Kt=8, 256 threads, 8x8 per thread. Global prefetch.
template<bool RELU, bool RES>
__global__ void __launch_bounds__(256) sgemm_kernel(
    const float* __restrict__ A, const float* __restrict__ B,
    const float* __restrict__ bias, const float* __restrict__ res,
    float* __restrict__ C, int M, int N, int K)
{
    __shared__ float As[8][128];
    __shared__ float Bs[8][128];

    const int tid = threadIdx.x;
    const int tx = tid & 15;     // 0..15 : column group
    const int ty = tid >> 4;     // 0..15 : row group
    const int bx = blockIdx.x;
    const int by = blockIdx.y;

    const float* Ab = A + (size_t)(by * 128) * K;
    const float* Bb = B + bx * 128;

    const int arow = tid >> 1, ac4 = (tid & 1) * 4;
    const int brow = tid >> 5, bc4 = (tid & 31) * 4;

    float acc[8][8];
    #pragma unroll
    for (int i = 0; i < 8; i++)
        #pragma unroll
        for (int j = 0; j < 8; j++) acc[i][j] = 0.f;

    float4 av = *(const float4*)(Ab + (size_t)arow * K + ac4);
    float4 bv = *(const float4*)(Bb + (size_t)brow * N + bc4);

    for (int kt = 0; kt < K; kt += 8) {
        As[ac4 + 0][arow] = av.x;
        As[ac4 + 1][arow] = av.y;
        As[ac4 + 2][arow] = av.z;
        As[ac4 + 3][arow] = av.w;
        *(float4*)&Bs[brow][bc4] = bv;
        __syncthreads();

        if (kt + 8 < K) {
            av = *(const float4*)(Ab + (size_t)arow * K + (kt + 8) + ac4);
            bv = *(const float4*)(Bb + (size_t)(kt + 8 + brow) * N + bc4);
        }

        #pragma unroll
        for (int kk = 0; kk < 8; kk++) {
            float a[8], b[8];
            *(float4*)&a[0] = *(const float4*)&As[kk][ty * 8];
            *(float4*)&a[4] = *(const float4*)&As[kk][ty * 8 + 4];
            *(float4*)&b[0] = *(const float4*)&Bs[kk][tx * 4];
            *(float4*)&b[4] = *(const float4*)&Bs[kk][64 + tx * 4];
            #pragma unroll
            for (int i = 0; i < 8; i++)
                #pragma unroll
                for (int j = 0; j < 8; j++)
                    acc[i][j] = fmaf(a[i], b[j], acc[i][j]);
        }
        __syncthreads();
    }

    #pragma unroll
    for (int i = 0; i < 8; i++) {
        const size_t r = (size_t)(by * 128 + ty * 8 + i);
        #pragma unroll
        for (int jh = 0; jh < 2; jh++) {
            const int c = bx * 128 + jh * 64 + tx * 4;
            float4 o;
            o.x = acc[i][jh * 4 + 0];
            o.y = acc[i][jh * 4 + 1];
            o.z = acc[i][jh * 4 + 2];
            o.w = acc[i][jh * 4 + 3];
            const float4 bb = *(const float4*)(bias + c);
            o.x += bb.x; o.y += bb.y; o.z += bb.z; o.w += bb.w;
            if (RES) {
                const float4 rv = *(const float4*)(res + r * N + c);
                o.x += rv.x; o.y += rv.y; o.z += rv.z; o.w += rv.w;
            }
            if (RELU) {
                o.x = fmaxf(o.x, 0.f); o.y = fmaxf(o.y, 0.f);
                o.z = fmaxf(o.z, 0.f); o.w = fmaxf(o.w, 0.f);
            }
            *(float4*)(C + r * N + c) = o;
        }
    }
}

// ---------------- Flash-style attention ------------------------------------
// Grid: (S/128, H, B). Block 256 threads. Q tile 128 x 64, K/V tiles 64 x 64.
// Thread map: tx = tid%8 owns k cols {j*8+tx} and out dims {tx*8..tx*8+7};
//             ty = tid/8 owns q rows {ty*4..ty*4+3}.
#define QTILE 128
#define KTILE 64
#define QS 68     // Qs row stride (floats)
#define KS 68     // Ks row stride
#define VS 64     // Vs row stride
#define PS 68     // Ps row stride
#define ATTN_SMEM ((QTILE*QS + KTILE*KS + KTILE*VS + QTILE*PS + KTILE) * 4)

__global__ void __launch_bounds__(256) attn_kernel(
    const float* __restrict__ Q, const float* __restrict__ K,
    const float* __restrict__ V, const int* __restrict__ mask,
    float* __restrict__ O)
{
    extern __shared__ float sm[];
    float* Qs = sm;                        // 128*68
    float* Ks = Qs + QTILE * QS;           // 64*68
    float* Vs = Ks + KTILE * KS;           // 64*64
    float* Ps = Vs + KTILE * VS;           // 128*68
    float* Ms = Ps + QTILE * PS;           // 64

    const int b  = blockIdx.z;
    const int h  = blockIdx.y;
    const int q0 = blockIdx.x * QTILE;
    const int tid = threadIdx.x;
    const int tx = tid & 7;
    const int ty = tid >> 3;

    // Load Q tile (128 x 64 floats = 2048 float4)
    const size_t baseQ = ((size_t)(b * S_LEN + q0)) * D_MODEL + h * DK;
    #pragma unroll
    for (int p = 0; p < 8; p++) {
        const int f = p * 256 + tid;
        const int r = f >> 4, c4 = f & 15;
        *(float4*)&Qs[r * QS + c4 * 4] =
            *(const float4*)(Q + baseQ + (size_t)r * D_MODEL + c4 * 4);
    }

    float m[4], l[4];
    #pragma unroll
    for (int i = 0; i < 4; i++) { m[i] = -1e30f; l[i] = 0.f; }
    float acc[4][8];
    #pragma unroll
    for (int i = 0; i < 4; i++)
        #pragma unroll
        for (int j = 0; j < 8; j++) acc[i][j] = 0.f;

    __syncthreads();

    for (int kt = 0; kt < S_LEN; kt += KTILE) {
        // Load K/V tiles (64 x 64 each) + mask
        const size_t baseK = ((size_t)(b * S_LEN + kt)) * D_MODEL + h * DK;
        #pragma unroll
        for (int p = 0; p < 4; p++) {
            const int f = p * 256 + tid;
            const int r = f >> 4, c4 = f & 15;
            *(float4*)&Ks[r * KS + c4 * 4] =
                *(const float4*)(K + baseK + (size_t)r * D_MODEL + c4 * 4);
            *(float4*)&Vs[r * VS + c4 * 4] =
                *(const float4*)(V + baseK + (size_t)r * D_MODEL + c4 * 4);
        }
        if (tid < KTILE)
            Ms[tid] = (mask[b * S_LEN + kt + tid] == 0) ? -1e9f : 0.f;
        __syncthreads();

        // Scores: s[i][j] for q rows ty*4+i, k cols j*8+tx
        float s[4][8];
        #pragma unroll
        for (int i = 0; i < 4; i++)
            #pragma unroll
            for (int j = 0; j < 8; j++) s[i][j] = 0.f;

        #pragma unroll
        for (int d = 0; d < DK; d += 4) {
            float4 qv[4];
            #pragma unroll
            for (int i = 0; i < 4; i++)
                qv[i] = *(const float4*)&Qs[(ty * 4 + i) * QS + d];
            #pragma unroll
            for (int j = 0; j < 8; j++) {
                const float4 kv = *(const float4*)&Ks[(j * 8 + tx) * KS + d];
                #pragma unroll
                for (int i = 0; i < 4; i++) {
                    s[i][j] = fmaf(qv[i].x, kv.x, s[i][j]);
                    s[i][j] = fmaf(qv[i].y, kv.y, s[i][j]);
                    s[i][j] = fmaf(qv[i].z, kv.z, s[i][j]);
                    s[i][j] = fmaf(qv[i].w, kv.w, s[i][j]);
                }
            }
        }
        #pragma unroll
        for (int i = 0; i < 4; i++)
            #pragma unroll
            for (int j = 0; j < 8; j++)
                s[i][j] = s[i][j] * 0.125f + Ms[j * 8 + tx];

        // Online softmax (rows reduced across the 8 tx lanes)
        #pragma unroll
        for (int i = 0; i < 4; i++) {
            float rm = s[i][0];
            #pragma unroll
            for (int j = 1; j < 8; j++) rm = fmaxf(rm, s[i][j]);
            #pragma unroll
            for (int off = 1; off < 8; off <<= 1)
                rm = fmaxf(rm, __shfl_xor_sync(0xffffffffu, rm, off));
            const float newm = fmaxf(m[i], rm);
            const float factor = __expf(m[i] - newm);
            m[i] = newm;
            float rs = 0.f;
            #pragma unroll
            for (int j = 0; j < 8; j++) {
                s[i][j] = __expf(s[i][j] - newm);
                rs += s[i][j];
            }
            #pragma unroll
            for (int off = 1; off < 8; off <<= 1)
                rs += __shfl_xor_sync(0xffffffffu, rs, off);
            l[i] = l[i] * factor + rs;
            #pragma unroll
            for (int j = 0; j < 8; j++) acc[i][j] *= factor;
            #pragma unroll
            for (int j = 0; j < 8; j++)
                Ps[(ty * 4 + i) * PS + j * 8 + tx] = s[i][j];
        }
        __syncthreads();

        // O += P @ V : thread owns (q rows ty*4+i) x (d cols tx*8..+7)
        #pragma unroll
        for (int j = 0; j < KTILE; j += 4) {
            float pa[4][4];
            #pragma unroll
            for (int i = 0; i < 4; i++)
                *(float4*)&pa[i][0] = *(const float4*)&Ps[(ty * 4 + i) * PS + j];
            #pragma unroll
            for (int jj = 0; jj < 4; jj++) {
                const float4 v0 = *(const float4*)&Vs[(j + jj) * VS + tx * 8];
                const float4 v1 = *(const float4*)&Vs[(j + jj) * VS + tx * 8 + 4];
                #pragma unroll
                for (int i = 0; i < 4; i++) {
                    const float p = pa[i][jj];
                    acc[i][0] = fmaf(p, v0.x, acc[i][0]);
                    acc[i][1] = fmaf(p, v0.y, acc[i][1]);
                    acc[i][2] = fmaf(p, v0.z, acc[i][2]);
                    acc[i][3] = fmaf(p, v0.w, acc[i][3]);
                    acc[i][4] = fmaf(p, v1.x, acc[i][4]);
                    acc[i][5] = fmaf(p, v1.y, acc[i][5]);
                    acc[i][6] = fmaf(p, v1.z, acc[i][6]);
                    acc[i][7] = fmaf(p, v1.w, acc[i][7]);
                }
            }
        }
        __syncthreads();
    }

    // Finalize: ctx[b, q, h*64 + d] = acc / l
    #pragma unroll
    for (int i = 0; i < 4; i++) {
        const float invl = 1.0f / l[i];
        const size_t q = (size_t)(b * S_LEN + q0 + ty * 4 + i);
        float* orow = O + q * D_MODEL + h * DK + tx * 8;
        float4 o0, o1;
        o0.x = acc[i][0] * invl; o0.y = acc[i][1] * invl;
        o0.z = acc[i][2] * invl; o0.w = acc[i][3] * invl;
        o1.x = acc[i][4] * invl; o1.y = acc[i][5] * invl;
        o1.z = acc[i][6] * invl; o1.w = acc[i][7] * invl;
        *(float4*)orow = o0;
        *(float4*)(orow + 4) = o1;
    }
}

// ---------------- launch ---------------------------------------------------
extern "C" void kernel_launch(void* const* d_in, const int* in_sizes, int n_in,
                              void* d_out, int out_size)
{
    const float* x   = (const float*)d_in[0];
    const int*   msk = (const int*)  d_in[1];
    const float* wq  = (const float*)d_in[2];
    const float* bq  = (const float*)d_in[3];
    const float* wk  = (const float*)d_in[4];
    const float* bk  = (const float*)d_in[5];
    const float* wv  = (const float*)d_in[6];
    const float* bv  = (const float*)d_in[7];
    const float* wo  = (const float*)d_in[8];
    const float* bo  = (const float*)d_in[9];
    const float* w1  = (const float*)d_in[10];
    const float* b1  = (const float*)d_in[11];
    const float* w2  = (const float*)d_in[12];
    const float* b2  = (const float*)d_in[13];
    const float* l1a = (const float*)d_in[14];
    const float* l1b = (const float*)d_in[15];
    const float* l2a = (const float*)d_in[16];
    const float* l2b = (const float*)d_in[17];
    float* out = (float*)d_out;

    float *xn, *q, *k, *v, *ctx, *h, *xn2, *mid;
    cudaGetSymbolAddress((void**)&xn,  g_xn);
    cudaGetSymbolAddress((void**)&q,   g_q);
    cudaGetSymbolAddress((void**)&k,   g_k);
    cudaGetSymbolAddress((void**)&v,   g_v);
    cudaGetSymbolAddress((void**)&ctx, g_ctx);
    cudaGetSymbolAddress((void**)&h,   g_h);
    cudaGetSymbolAddress((void**)&xn2, g_xn2);
    cudaGetSymbolAddress((void**)&mid, g_mid);

    cudaFuncSetAttribute(attn_kernel,
        cudaFuncAttributeMaxDynamicSharedMemorySize, ATTN_SMEM);

    // 1. ln1
    ln_kernel<<<M_ROWS, 256>>>(x, l1a, l1b, xn);
    // 2. QKV projections
    sgemm_kernel<false, false><<<dim3(D_MODEL/128, M_ROWS/128), 256>>>(
        xn, wq, bq, nullptr, q, M_ROWS, D_MODEL, D_MODEL);
    sgemm_kernel<false, false><<<dim3(D_MODEL/128, M_ROWS/128), 256>>>(
        xn, wk, bk, nullptr, k, M_ROWS, D_MODEL, D_MODEL);
    sgemm_kernel<false, false><<<dim3(D_MODEL/128, M_ROWS/128), 256>>>(
        xn, wv, bv, nullptr, v, M_ROWS, D_MODEL, D_MODEL);
    // 3. attention
    attn_kernel<<<dim3(S_LEN/QTILE, N_HEADS, B_SZ), 256, ATTN_SMEM>>>(
        q, k, v, msk, ctx);
    // 4. output projection + residual with x
    sgemm_kernel<false, true><<<dim3(D_MODEL/128, M_ROWS/128), 256>>>(
        ctx, wo, bo, x, h, M_ROWS, D_MODEL, D_MODEL);
    // 5. ln2
    ln_kernel<<<M_ROWS, 256>>>(h, l2a, l2b, xn2);
    // 6. FFN up + relu
    sgemm_kernel<true, false><<<dim3(F_FFN/128, M_ROWS/128), 256>>>(
        xn2, w1, b1, nullptr, mid, M_ROWS, F_FFN, D_MODEL);
    // 7. FFN down + residual with h -> out
    sgemm_kernel<false, true><<<dim3(D_MODEL/128, M_ROWS/128), 256>>>(
        mid, w2, b2, h, out, M_ROWS, D_MODEL, F_FFN);
}

// round 4
// speedup vs baseline: 1.0001x; 1.0001x over previous
#include <cuda_runtime.h>
#include <math.h>

#define D_MODEL 1024
#define F_FFN   4096
#define B_SZ    4
#define S_LEN   2048
#define N_HEADS 16
#define DK      64
#define M_ROWS  (B_SZ * S_LEN)   // 8192
#define LN_EPS  1e-6f

// ---------------- scratch (no allocs allowed) ----------------
__device__ float g_xn [(size_t)M_ROWS * D_MODEL];
__device__ float g_q  [(size_t)M_ROWS * D_MODEL];
__device__ float g_k  [(size_t)M_ROWS * D_MODEL];
__device__ float g_v  [(size_t)M_ROWS * D_MODEL];
__device__ float g_ctx[(size_t)M_ROWS * D_MODEL];
__device__ float g_h  [(size_t)M_ROWS * D_MODEL];
__device__ float g_xn2[(size_t)M_ROWS * D_MODEL];
__device__ float g_mid[(size_t)M_ROWS * F_FFN];

// ---------------- LayerNorm (torch semantics: ddof=1, eps added to std) ----
__global__ void __launch_bounds__(256) ln_kernel(
    const float* __restrict__ x,
    const float* __restrict__ alpha,
    const float* __restrict__ beta,
    float* __restrict__ out)
{
    __shared__ float red[32];
    const int row = blockIdx.x;
    const int tid = threadIdx.x;

    const float4 v = ((const float4*)(x + (size_t)row * D_MODEL))[tid];
    float s  = v.x + v.y + v.z + v.w;
    float s2 = v.x * v.x + v.y * v.y + v.z * v.z + v.w * v.w;
    #pragma unroll
    for (int off = 16; off > 0; off >>= 1) {
        s  += __shfl_xor_sync(0xffffffffu, s,  off);
        s2 += __shfl_xor_sync(0xffffffffu, s2, off);
    }
    const int warp = tid >> 5;
    if ((tid & 31) == 0) { red[warp] = s; red[8 + warp] = s2; }
    __syncthreads();
    if (tid == 0) {
        float ts = 0.f, ts2 = 0.f;
        #pragma unroll
        for (int i = 0; i < 8; i++) { ts += red[i]; ts2 += red[8 + i]; }
        const float mean = ts * (1.0f / (float)D_MODEL);
        float var = (ts2 - (float)D_MODEL * mean * mean) * (1.0f / (float)(D_MODEL - 1));
        var = fmaxf(var, 0.0f);
        red[16] = mean;
        red[17] = 1.0f / (sqrtf(var) + LN_EPS);
    }
    __syncthreads();
    const float mean = red[16], inv = red[17];
    const float4 a = ((const float4*)alpha)[tid];
    const float4 b = ((const float4*)beta)[tid];
    float4 o;
    o.x = a.x * (v.x - mean) * inv + b.x;
    o.y = a.y * (v.y - mean) * inv + b.y;
    o.z = a.z * (v.z - mean) * inv + b.z;
    o.w = a.w * (v.w - mean) * inv + b.w;
    ((float4*)(out + (size_t)row * D_MODEL))[tid] = o;
}

// ---------------- SGEMM: C[M,N] = op(A[M,K] @ B[K,N] + bias [+ res]) --------
// 128x128 block tile, Kt=8, 256 threads, 8x8 per thread. Global prefetch.
template<bool RELU, bool RES>
__global__ void __launch_bounds__(256) sgemm_kernel(
    const float* __restrict__ A, const float* __restrict__ B,
    const float* __restrict__ bias, const float* __restrict__ res,
    float* __restrict__ C, int M, int N, int K)
{
    __shared__ float As[8][128];
    __shared__ float Bs[8][128];

    const int tid = threadIdx.x;
    const int tx = tid & 15;     // 0..15 : column group
    const int ty = tid >> 4;     // 0..15 : row group
    const int bx = blockIdx.x;
    const int by = blockIdx.y;

    const float* Ab = A + (size_t)(by * 128) * K;
    const float* Bb = B + bx * 128;

    const int arow = tid >> 1, ac4 = (tid & 1) * 4;
    const int brow = tid >> 5, bc4 = (tid & 31) * 4;

    float acc[8][8];
    #pragma unroll
    for (int i = 0; i < 8; i++)
        #pragma unroll
        for (int j = 0; j < 8; j++) acc[i][j] = 0.f;

    float4 av = *(const float4*)(Ab + (size_t)arow * K + ac4);
    float4 bv = *(const float4*)(Bb + (size_t)brow * N + bc4);

    for (int kt = 0; kt < K; kt += 8) {
        As[ac4 + 0][arow] = av.x;
        As[ac4 + 1][arow] = av.y;
        As[ac4 + 2][arow] = av.z;
        As[ac4 + 3][arow] = av.w;
        *(float4*)&Bs[brow][bc4] = bv;
        __syncthreads();

        if (kt + 8 < K) {
            av = *(const float4*)(Ab + (size_t)arow * K + (kt + 8) + ac4);
            bv = *(const float4*)(Bb + (size_t)(kt + 8 + brow) * N + bc4);
        }

        #pragma unroll
        for (int kk = 0; kk < 8; kk++) {
            float a[8], b[8];
            *(float4*)&a[0] = *(const float4*)&As[kk][ty * 8];
            *(float4*)&a[4] = *(const float4*)&As[kk][ty * 8 + 4];
            *(float4*)&b[0] = *(const float4*)&Bs[kk][tx * 4];
            *(float4*)&b[4] = *(const float4*)&Bs[kk][64 + tx * 4];
            #pragma unroll
            for (int i = 0; i < 8; i++)
                #pragma unroll
                for (int j = 0; j < 8; j++)
                    acc[i][j] = fmaf(a[i], b[j], acc[i][j]);
        }
        __syncthreads();
    }

    #pragma unroll
    for (int i = 0; i < 8; i++) {
        const size_t r = (size_t)(by * 128 + ty * 8 + i);
        #pragma unroll
        for (int jh = 0; jh < 2; jh++) {
            const int c = bx * 128 + jh * 64 + tx * 4;
            float4 o;
            o.x = acc[i][jh * 4 + 0];
            o.y = acc[i][jh * 4 + 1];
            o.z = acc[i][jh * 4 + 2];
            o.w = acc[i][jh * 4 + 3];
            const float4 bb = *(const float4*)(bias + c);
            o.x += bb.x; o.y += bb.y; o.z += bb.z; o.w += bb.w;
            if (RES) {
                const float4 rv = *(const float4*)(res + r * N + c);
                o.x += rv.x; o.y += rv.y; o.z += rv.z; o.w += rv.w;
            }
            if (RELU) {
                o.x = fmaxf(o.x, 0.f); o.y = fmaxf(o.y, 0.f);
                o.z = fmaxf(o.z, 0.f); o.w = fmaxf(o.w, 0.f);
            }
            *(float4*)(C + r * N + c) = o;
        }
    }
}

// ---------------- Flash-style attention ------------------------------------
// Grid: (S/128, H, B). Block 256 threads. Q tile 128 x 64, K/V tiles 64 x 64.
// Thread map: tx = tid%8 owns k cols {j*8+tx} and out dims {tx*8..tx*8+7};
//             ty = tid/8 owns q rows {ty*4..ty*4+3}.
#define QTILE 128
#define KTILE 64
#define QS 68     // Qs row stride (floats)
#define KS 68     // Ks row stride
#define VS 64     // Vs row stride
#define PS 68     // Ps row stride
#define ATTN_SMEM ((QTILE*QS + KTILE*KS + KTILE*VS + QTILE*PS + KTILE) * 4)

__global__ void __launch_bounds__(256) attn_kernel(
    const float* __restrict__ Q, const float* __restrict__ K,
    const float* __restrict__ V, const int* __restrict__ mask,
    float* __restrict__ O)
{
    extern __shared__ float sm[];
    float* Qs = sm;                        // 128*68
    float* Ks = Qs + QTILE * QS;           // 64*68
    float* Vs = Ks + KTILE * KS;           // 64*64
    float* Ps = Vs + KTILE * VS;           // 128*68
    float* Ms = Ps + QTILE * PS;           // 64

    const int b  = blockIdx.z;
    const int h  = blockIdx.y;
    const int q0 = blockIdx.x * QTILE;
    const int tid = threadIdx.x;
    const int tx = tid & 7;
    const int ty = tid >> 3;

    // Load Q tile (128 x 64 floats = 2048 float4)
    const size_t baseQ = ((size_t)(b * S_LEN + q0)) * D_MODEL + h * DK;
    #pragma unroll
    for (int p = 0; p < 8; p++) {
        const int f = p * 256 + tid;
        const int r = f >> 4, c4 = f & 15;
        *(float4*)&Qs[r * QS + c4 * 4] =
            *(const float4*)(Q + baseQ + (size_t)r * D_MODEL + c4 * 4);
    }

    float m[4], l[4];
    #pragma unroll
    for (int i = 0; i < 4; i++) { m[i] = -1e30f; l[i] = 0.f; }
    float acc[4][8];
    #pragma unroll
    for (int i = 0; i < 4; i++)
        #pragma unroll
        for (int j = 0; j < 8; j++) acc[i][j] = 0.f;

    __syncthreads();

    for (int kt = 0; kt < S_LEN; kt += KTILE) {
        // Load K/V tiles (64 x 64 each) + mask
        const size_t baseK = ((size_t)(b * S_LEN + kt)) * D_MODEL + h * DK;
        #pragma unroll
        for (int p = 0; p < 4; p++) {
            const int f = p * 256 + tid;
            const int r = f >> 4, c4 = f & 15;
            *(float4*)&Ks[r * KS + c4 * 4] =
                *(const float4*)(K + baseK + (size_t)r * D_MODEL + c4 * 4);
            *(float4*)&Vs[r * VS + c4 * 4] =
                *(const float4*)(V + baseK + (size_t)r * D_MODEL + c4 * 4);
        }
        if (tid < KTILE)
            Ms[tid] = (mask[b * S_LEN + kt + tid] == 0) ? -1e9f : 0.f;
        __syncthreads();

        // Scores: s[i][j] for q rows ty*4+i, k cols j*8+tx
        float s[4][8];
        #pragma unroll
        for (int i = 0; i < 4; i++)
            #pragma unroll
            for (int j = 0; j < 8; j++) s[i][j] = 0.f;

        #pragma unroll
        for (int d = 0; d < DK; d += 4) {
            float4 qv[4];
            #pragma unroll
            for (int i = 0; i < 4; i++)
                qv[i] = *(const float4*)&Qs[(ty * 4 + i) * QS + d];
            #pragma unroll
            for (int j = 0; j < 8; j++) {
                const float4 kv = *(const float4*)&Ks[(j * 8 + tx) * KS + d];
                #pragma unroll
                for (int i = 0; i < 4; i++) {
                    s[i][j] = fmaf(qv[i].x, kv.x, s[i][j]);
                    s[i][j] = fmaf(qv[i].y, kv.y, s[i][j]);
                    s[i][j] = fmaf(qv[i].z, kv.z, s[i][j]);
                    s[i][j] = fmaf(qv[i].w, kv.w, s[i][j]);
                }
            }
        }
        #pragma unroll
        for (int i = 0; i < 4; i++)
            #pragma unroll
            for (int j = 0; j < 8; j++)
                s[i][j] = s[i][j] * 0.125f + Ms[j * 8 + tx];

        // Online softmax (rows reduced across the 8 tx lanes)
        #pragma unroll
        for (int i = 0; i < 4; i++) {
            float rm = s[i][0];
            #pragma unroll
            for (int j = 1; j < 8; j++) rm = fmaxf(rm, s[i][j]);
            #pragma unroll
            for (int off = 1; off < 8; off <<= 1)
                rm = fmaxf(rm, __shfl_xor_sync(0xffffffffu, rm, off));
            const float newm = fmaxf(m[i], rm);
            const float factor = __expf(m[i] - newm);
            m[i] = newm;
            float rs = 0.f;
            #pragma unroll
            for (int j = 0; j < 8; j++) {
                s[i][j] = __expf(s[i][j] - newm);
                rs += s[i][j];
            }
            #pragma unroll
            for (int off = 1; off < 8; off <<= 1)
                rs += __shfl_xor_sync(0xffffffffu, rs, off);
            l[i] = l[i] * factor + rs;
            #pragma unroll
            for (int j = 0; j < 8; j++) acc[i][j] *= factor;
            #pragma unroll
            for (int j = 0; j < 8; j++)
                Ps[(ty * 4 + i) * PS + j * 8 + tx] = s[i][j];
        }
        __syncthreads();

        // O += P @ V : thread owns (q rows ty*4+i) x (d cols tx*8..+7)
        #pragma unroll
        for (int j = 0; j < KTILE; j += 4) {
            float pa[4][4];
            #pragma unroll
            for (int i = 0; i < 4; i++)
                *(float4*)&pa[i][0] = *(const float4*)&Ps[(ty * 4 + i) * PS + j];
            #pragma unroll
            for (int jj = 0; jj < 4; jj++) {
                const float4 v0 = *(const float4*)&Vs[(j + jj) * VS + tx * 8];
                const float4 v1 = *(const float4*)&Vs[(j + jj) * VS + tx * 8 + 4];
                #pragma unroll
                for (int i = 0; i < 4; i++) {
                    const float p = pa[i][jj];
                    acc[i][0] = fmaf(p, v0.x, acc[i][0]);
                    acc[i][1] = fmaf(p, v0.y, acc[i][1]);
                    acc[i][2] = fmaf(p, v0.z, acc[i][2]);
                    acc[i][3] = fmaf(p, v0.w, acc[i][3]);
                    acc[i][4] = fmaf(p, v1.x, acc[i][4]);
                    acc[i][5] = fmaf(p, v1.y, acc[i][5]);
                    acc[i][6] = fmaf(p, v1.z, acc[i][6]);
                    acc[i][7] = fmaf(p, v1.w, acc[i][7]);
                }
            }
        }
        __syncthreads();
    }

    // Finalize: ctx[b, q, h*64 + d] = acc / l
    #pragma unroll
    for (int i = 0; i < 4; i++) {
        const float invl = 1.0f / l[i];
        const size_t q = (size_t)(b * S_LEN + q0 + ty * 4 + i);
        float* orow = O + q * D_MODEL + h * DK + tx * 8;
        float4 o0, o1;
        o0.x = acc[i][0] * invl; o0.y = acc[i][1] * invl;
        o0.z = acc[i][2] * invl; o0.w = acc[i][3] * invl;
        o1.x = acc[i][4] * invl; o1.y = acc[i][5] * invl;
        o1.z = acc[i][6] * invl; o1.w = acc[i][7] * invl;
        *(float4*)orow = o0;
        *(float4*)(orow + 4) = o1;
    }
}

// ---------------- launch ---------------------------------------------------
extern "C" void kernel_launch(void* const* d_in, const int* in_sizes, int n_in,
                              void* d_out, int out_size)
{
    const float* x   = (const float*)d_in[0];
    const int*   msk = (const int*)  d_in[1];
    const float* wq  = (const float*)d_in[2];
    const float* bq  = (const float*)d_in[3];
    const float* wk  = (const float*)d_in[4];
    const float* bk  = (const float*)d_in[5];
    const float* wv  = (const float*)d_in[6];
    const float* bv  = (const float*)d_in[7];
    const float* wo  = (const float*)d_in[8];
    const float* bo  = (const float*)d_in[9];
    const float* w1  = (const float*)d_in[10];
    const float* b1  = (const float*)d_in[11];
    const float* w2  = (const float*)d_in[12];
    const float* b2  = (const float*)d_in[13];
    const float* l1a = (const float*)d_in[14];
    const float* l1b = (const float*)d_in[15];
    const float* l2a = (const float*)d_in[16];
    const float* l2b = (const float*)d_in[17];
    float* out = (float*)d_out;

    float *xn, *q, *k, *v, *ctx, *h, *xn2, *mid;
    cudaGetSymbolAddress((void**)&xn,  g_xn);
    cudaGetSymbolAddress((void**)&q,   g_q);
    cudaGetSymbolAddress((void**)&k,   g_k);
    cudaGetSymbolAddress((void**)&v,   g_v);
    cudaGetSymbolAddress((void**)&ctx, g_ctx);
    cudaGetSymbolAddress((void**)&h,   g_h);
    cudaGetSymbolAddress((void**)&xn2, g_xn2);
    cudaGetSymbolAddress((void**)&mid, g_mid);

    cudaFuncSetAttribute(attn_kernel,
        cudaFuncAttributeMaxDynamicSharedMemorySize, ATTN_SMEM);

    // 1. ln1
    ln_kernel<<<M_ROWS, 256>>>(x, l1a, l1b, xn);
    // 2. QKV projections
    sgemm_kernel<false, false><<<dim3(D_MODEL/128, M_ROWS/128), 256>>>(
        xn, wq, bq, nullptr, q, M_ROWS, D_MODEL, D_MODEL);
    sgemm_kernel<false, false><<<dim3(D_MODEL/128, M_ROWS/128), 256>>>(
        xn, wk, bk, nullptr, k, M_ROWS, D_MODEL, D_MODEL);
    sgemm_kernel<false, false><<<dim3(D_MODEL/128, M_ROWS/128), 256>>>(
        xn, wv, bv, nullptr, v, M_ROWS, D_MODEL, D_MODEL);
    // 3. attention
    attn_kernel<<<dim3(S_LEN/QTILE, N_HEADS, B_SZ), 256, ATTN_SMEM>>>(
        q, k, v, msk, ctx);
    // 4. output projection + residual with x
    sgemm_kernel<false, true><<<dim3(D_MODEL/128, M_ROWS/128), 256>>>(
        ctx, wo, bo, x, h, M_ROWS, D_MODEL, D_MODEL);
    // 5. ln2
    ln_kernel<<<M_ROWS, 256>>>(h, l2a, l2b, xn2);
    // 6. FFN up + relu
    sgemm_kernel<true, false><<<dim3(F_FFN/128, M_ROWS/128), 256>>>(
        xn2, w1, b1, nullptr, mid, M_ROWS, F_FFN, D_MODEL);
    // 7. FFN down + residual with h -> out
    sgemm_kernel<false, true><<<dim3(D_MODEL/128, M_ROWS/128), 256>>>(
        mid, w2, b2, h, out, M_ROWS, D_MODEL, F_FFN);
}

// round 5
// speedup vs baseline: 1.1476x; 1.1475x over previous
#include <cuda_runtime.h>
#include <cuda_bf16.h>
#include <math.h>
#include <stdint.h>

#define D_MODEL 1024
#define F_FFN   4096
#define B_SZ    4
#define S_LEN   2048
#define N_HEADS 16
#define DK      64
#define M_ROWS  (B_SZ * S_LEN)   // 8192
#define LN_EPS  1e-6f

// ---------------- scratch (no allocs allowed) ----------------
__device__ float g_xn [(size_t)M_ROWS * D_MODEL];
__device__ float g_q  [(size_t)M_ROWS * D_MODEL];
__device__ float g_k  [(size_t)M_ROWS * D_MODEL];
__device__ float g_v  [(size_t)M_ROWS * D_MODEL];
__device__ float g_ctx[(size_t)M_ROWS * D_MODEL];
__device__ float g_h  [(size_t)M_ROWS * D_MODEL];
__device__ float g_xn2[(size_t)M_ROWS * D_MODEL];
__device__ float g_mid[(size_t)M_ROWS * F_FFN];

// ---------------- LayerNorm (torch semantics: ddof=1, eps added to std) ----
__global__ void __launch_bounds__(256) ln_kernel(
    const float* __restrict__ x,
    const float* __restrict__ alpha,
    const float* __restrict__ beta,
    float* __restrict__ out)
{
    __shared__ float red[32];
    const int row = blockIdx.x;
    const int tid = threadIdx.x;

    const float4 v = ((const float4*)(x + (size_t)row * D_MODEL))[tid];
    float s  = v.x + v.y + v.z + v.w;
    float s2 = v.x * v.x + v.y * v.y + v.z * v.z + v.w * v.w;
    #pragma unroll
    for (int off = 16; off > 0; off >>= 1) {
        s  += __shfl_xor_sync(0xffffffffu, s,  off);
        s2 += __shfl_xor_sync(0xffffffffu, s2, off);
    }
    const int warp = tid >> 5;
    if ((tid & 31) == 0) { red[warp] = s; red[8 + warp] = s2; }
    __syncthreads();
    if (tid == 0) {
        float ts = 0.f, ts2 = 0.f;
        #pragma unroll
        for (int i = 0; i < 8; i++) { ts += red[i]; ts2 += red[8 + i]; }
        const float mean = ts * (1.0f / (float)D_MODEL);
        float var = (ts2 - (float)D_MODEL * mean * mean) * (1.0f / (float)(D_MODEL - 1));
        var = fmaxf(var, 0.0f);
        red[16] = mean;
        red[17] = 1.0f / (sqrtf(var) + LN_EPS);
    }
    __syncthreads();
    const float mean = red[16], inv = red[17];
    const float4 a = ((const float4*)alpha)[tid];
    const float4 b = ((const float4*)beta)[tid];
    float4 o;
    o.x = a.x * (v.x - mean) * inv + b.x;
    o.y = a.y * (v.y - mean) * inv + b.y;
    o.z = a.z * (v.z - mean) * inv + b.z;
    o.w = a.w * (v.w - mean) * inv + b.w;
    ((float4*)(out + (size_t)row * D_MODEL))[tid] = o;
}

// ---------------- Tensor-core GEMM via bf16 split -------------------------
// C[M,N] = A[M,K] @ B[K,N] + bias [+res] [relu]
// fp32 inputs split as x = hi + lo (bf16 each); D = Ah*Bh + Ah*Bl + Al*Bh.
// Block tile 128x128, K-tile 32, 256 threads = 8 warps (4M x 2N),
// warp tile 32(M) x 64(N) via mma.sync.m16n8k16.
#define ASTR 40    // As row stride in bf16 (80B: conflict-free ldmatrix)
#define BSTR 136   // Bs row stride in bf16 (272B: conflict-free ldmatrix.trans)

__device__ __forceinline__ uint32_t smem_u32(const void* p) {
    return (uint32_t)__cvta_generic_to_shared(p);
}

#define LDSM_X4(r0,r1,r2,r3,addr) \
    asm volatile("ldmatrix.sync.aligned.m8n8.x4.shared.b16 {%0,%1,%2,%3},[%4];" \
        : "=r"(r0), "=r"(r1), "=r"(r2), "=r"(r3) : "r"(addr))

#define LDSM_X4T(r0,r1,r2,r3,addr) \
    asm volatile("ldmatrix.sync.aligned.m8n8.x4.trans.shared.b16 {%0,%1,%2,%3},[%4];" \
        : "=r"(r0), "=r"(r1), "=r"(r2), "=r"(r3) : "r"(addr))

#define MMA16816(c,a,b0,b1) \
    asm volatile("mma.sync.aligned.m16n8k16.row.col.f32.bf16.bf16.f32 " \
        "{%0,%1,%2,%3},{%4,%5,%6,%7},{%8,%9},{%0,%1,%2,%3};" \
        : "+f"((c)[0]), "+f"((c)[1]), "+f"((c)[2]), "+f"((c)[3]) \
        : "r"((a)[0]), "r"((a)[1]), "r"((a)[2]), "r"((a)[3]), "r"(b0), "r"(b1))

__device__ __forceinline__ void split2(float x, __nv_bfloat16& h, __nv_bfloat16& l) {
    h = __float2bfloat16(x);
    l = __float2bfloat16(x - __bfloat162float(h));
}

template<bool RELU, bool RES>
__global__ void __launch_bounds__(256) mma_gemm(
    const float* __restrict__ A, const float* __restrict__ B,
    const float* __restrict__ bias, const float* __restrict__ res,
    float* __restrict__ C, int M, int N, int K)
{
    __shared__ __nv_bfloat16 As_hi[128 * ASTR];
    __shared__ __nv_bfloat16 As_lo[128 * ASTR];
    __shared__ __nv_bfloat16 Bs_hi[32 * BSTR];
    __shared__ __nv_bfloat16 Bs_lo[32 * BSTR];

    const int tid  = threadIdx.x;
    const int lane = tid & 31;
    const int wid  = tid >> 5;
    const int wm   = (wid & 3) * 32;   // warp M offset (4 warps in M)
    const int wn   = (wid >> 2) * 64;  // warp N offset (2 warps in N)
    const int bx = blockIdx.x, by = blockIdx.y;

    const float* Ab = A + (size_t)(by * 128) * K;
    const float* Bb = B + bx * 128;

    // gmem staging map: A tile 128x32 (2 thr/row x 4 float4), B tile 32x128
    const int a_row = tid >> 1, a_c0 = (tid & 1) * 16;
    const int b_row = tid >> 3, b_c0 = (tid & 7) * 16;

    // ldmatrix address components
    const int lane16 = lane & 15;
    const int lane8  = (lane >> 4) * 8;
    const uint32_t ash = smem_u32(As_hi), asl = smem_u32(As_lo);
    const uint32_t bsh = smem_u32(Bs_hi), bsl = smem_u32(Bs_lo);
    const uint32_t a_off = ((wm + lane16) * ASTR + lane8) * 2;
    const uint32_t b_off = (lane16 * BSTR + wn + lane8) * 2;

    float acc[2][8][4];
    #pragma unroll
    for (int i = 0; i < 2; i++)
        #pragma unroll
        for (int j = 0; j < 8; j++)
            #pragma unroll
            for (int q = 0; q < 4; q++) acc[i][j][q] = 0.f;

    float4 av[4], bv[4];
    #pragma unroll
    for (int i = 0; i < 4; i++) {
        av[i] = *(const float4*)(Ab + (size_t)a_row * K + a_c0 + i * 4);
        bv[i] = *(const float4*)(Bb + (size_t)b_row * N + b_c0 + i * 4);
    }

    for (int kt = 0; kt < K; kt += 32) {
        __syncthreads();
        #pragma unroll
        for (int i = 0; i < 4; i++) {
            const int ac = a_c0 + i * 4;
            split2(av[i].x, As_hi[a_row * ASTR + ac + 0], As_lo[a_row * ASTR + ac + 0]);
            split2(av[i].y, As_hi[a_row * ASTR + ac + 1], As_lo[a_row * ASTR + ac + 1]);
            split2(av[i].z, As_hi[a_row * ASTR + ac + 2], As_lo[a_row * ASTR + ac + 2]);
            split2(av[i].w, As_hi[a_row * ASTR + ac + 3], As_lo[a_row * ASTR + ac + 3]);
            const int bc = b_c0 + i * 4;
            split2(bv[i].x, Bs_hi[b_row * BSTR + bc + 0], Bs_lo[b_row * BSTR + bc + 0]);
            split2(bv[i].y, Bs_hi[b_row * BSTR + bc + 1], Bs_lo[b_row * BSTR + bc + 1]);
            split2(bv[i].z, Bs_hi[b_row * BSTR + bc + 2], Bs_lo[b_row * BSTR + bc + 2]);
            split2(bv[i].w, Bs_hi[b_row * BSTR + bc + 3], Bs_lo[b_row * BSTR + bc + 3]);
        }
        __syncthreads();

        if (kt + 32 < K) {
            #pragma unroll
            for (int i = 0; i < 4; i++) {
                av[i] = *(const float4*)(Ab + (size_t)a_row * K + (kt + 32) + a_c0 + i * 4);
                bv[i] = *(const float4*)(Bb + (size_t)(kt + 32 + b_row) * N + b_c0 + i * 4);
            }
        }

        #pragma unroll
        for (int ks = 0; ks < 2; ks++) {
            uint32_t ah[2][4], al[2][4];
            #pragma unroll
            for (int mf = 0; mf < 2; mf++) {
                const uint32_t ao = a_off + (mf * 16 * ASTR + ks * 16) * 2;
                LDSM_X4(ah[mf][0], ah[mf][1], ah[mf][2], ah[mf][3], ash + ao);
                LDSM_X4(al[mf][0], al[mf][1], al[mf][2], al[mf][3], asl + ao);
            }
            #pragma unroll
            for (int nf2 = 0; nf2 < 4; nf2++) {
                uint32_t bh[4], bl[4];
                const uint32_t bo = b_off + (ks * 16 * BSTR + nf2 * 16) * 2;
                LDSM_X4T(bh[0], bh[1], bh[2], bh[3], bsh + bo);
                LDSM_X4T(bl[0], bl[1], bl[2], bl[3], bsl + bo);
                #pragma unroll
                for (int mf = 0; mf < 2; mf++) {
                    #pragma unroll
                    for (int h = 0; h < 2; h++) {
                        float* c = acc[mf][nf2 * 2 + h];
                        MMA16816(c, ah[mf], bh[2 * h], bh[2 * h + 1]);
                        MMA16816(c, ah[mf], bl[2 * h], bl[2 * h + 1]);
                        MMA16816(c, al[mf], bh[2 * h], bh[2 * h + 1]);
                    }
                }
            }
        }
    }

    // Epilogue: c0,c1 -> (row g, col 2t/2t+1); c2,c3 -> (row g+8, ...)
    const int g = lane >> 2, t = lane & 3;
    #pragma unroll
    for (int mf = 0; mf < 2; mf++) {
        #pragma unroll
        for (int nf = 0; nf < 8; nf++) {
            const int col = bx * 128 + wn + nf * 8 + t * 2;
            const float2 bb = *(const float2*)(bias + col);
            #pragma unroll
            for (int half = 0; half < 2; half++) {
                const size_t r = (size_t)(by * 128 + wm + mf * 16 + g + half * 8);
                float2 o;
                o.x = acc[mf][nf][half * 2 + 0] + bb.x;
                o.y = acc[mf][nf][half * 2 + 1] + bb.y;
                if (RES) {
                    const float2 rv = *(const float2*)(res + r * N + col);
                    o.x += rv.x; o.y += rv.y;
                }
                if (RELU) { o.x = fmaxf(o.x, 0.f); o.y = fmaxf(o.y, 0.f); }
                *(float2*)(C + r * N + col) = o;
            }
        }
    }
}

// ---------------- Flash-style attention ------------------------------------
#define QTILE 128
#define KTILE 64
#define QS 68
#define KS 68
#define VS 64
#define PS 68
#define ATTN_SMEM ((QTILE*QS + KTILE*KS + KTILE*VS + QTILE*PS + KTILE) * 4)

__global__ void __launch_bounds__(256) attn_kernel(
    const float* __restrict__ Q, const float* __restrict__ K,
    const float* __restrict__ V, const int* __restrict__ mask,
    float* __restrict__ O)
{
    extern __shared__ float sm[];
    float* Qs = sm;
    float* Ks = Qs + QTILE * QS;
    float* Vs = Ks + KTILE * KS;
    float* Ps = Vs + KTILE * VS;
    float* Ms = Ps + QTILE * PS;

    const int b  = blockIdx.z;
    const int h  = blockIdx.y;
    const int q0 = blockIdx.x * QTILE;
    const int tid = threadIdx.x;
    const int tx = tid & 7;
    const int ty = tid >> 3;

    const size_t baseQ = ((size_t)(b * S_LEN + q0)) * D_MODEL + h * DK;
    #pragma unroll
    for (int p = 0; p < 8; p++) {
        const int f = p * 256 + tid;
        const int r = f >> 4, c4 = f & 15;
        *(float4*)&Qs[r * QS + c4 * 4] =
            *(const float4*)(Q + baseQ + (size_t)r * D_MODEL + c4 * 4);
    }

    float m[4], l[4];
    #pragma unroll
    for (int i = 0; i < 4; i++) { m[i] = -1e30f; l[i] = 0.f; }
    float acc[4][8];
    #pragma unroll
    for (int i = 0; i < 4; i++)
        #pragma unroll
        for (int j = 0; j < 8; j++) acc[i][j] = 0.f;

    __syncthreads();

    for (int kt = 0; kt < S_LEN; kt += KTILE) {
        const size_t baseK = ((size_t)(b * S_LEN + kt)) * D_MODEL + h * DK;
        #pragma unroll
        for (int p = 0; p < 4; p++) {
            const int f = p * 256 + tid;
            const int r = f >> 4, c4 = f & 15;
            *(float4*)&Ks[r * KS + c4 * 4] =
                *(const float4*)(K + baseK + (size_t)r * D_MODEL + c4 * 4);
            *(float4*)&Vs[r * VS + c4 * 4] =
                *(const float4*)(V + baseK + (size_t)r * D_MODEL + c4 * 4);
        }
        if (tid < KTILE)
            Ms[tid] = (mask[b * S_LEN + kt + tid] == 0) ? -1e9f : 0.f;
        __syncthreads();

        float s[4][8];
        #pragma unroll
        for (int i = 0; i < 4; i++)
            #pragma unroll
            for (int j = 0; j < 8; j++) s[i][j] = 0.f;

        #pragma unroll
        for (int d = 0; d < DK; d += 4) {
            float4 qv[4];
            #pragma unroll
            for (int i = 0; i < 4; i++)
                qv[i] = *(const float4*)&Qs[(ty * 4 + i) * QS + d];
            #pragma unroll
            for (int j = 0; j < 8; j++) {
                const float4 kv = *(const float4*)&Ks[(j * 8 + tx) * KS + d];
                #pragma unroll
                for (int i = 0; i < 4; i++) {
                    s[i][j] = fmaf(qv[i].x, kv.x, s[i][j]);
                    s[i][j] = fmaf(qv[i].y, kv.y, s[i][j]);
                    s[i][j] = fmaf(qv[i].z, kv.z, s[i][j]);
                    s[i][j] = fmaf(qv[i].w, kv.w, s[i][j]);
                }
            }
        }
        #pragma unroll
        for (int i = 0; i < 4; i++)
            #pragma unroll
            for (int j = 0; j < 8; j++)
                s[i][j] = s[i][j] * 0.125f + Ms[j * 8 + tx];

        #pragma unroll
        for (int i = 0; i < 4; i++) {
            float rm = s[i][0];
            #pragma unroll
            for (int j = 1; j < 8; j++) rm = fmaxf(rm, s[i][j]);
            #pragma unroll
            for (int off = 1; off < 8; off <<= 1)
                rm = fmaxf(rm, __shfl_xor_sync(0xffffffffu, rm, off));
            const float newm = fmaxf(m[i], rm);
            const float factor = __expf(m[i] - newm);
            m[i] = newm;
            float rs = 0.f;
            #pragma unroll
            for (int j = 0; j < 8; j++) {
                s[i][j] = __expf(s[i][j] - newm);
                rs += s[i][j];
            }
            #pragma unroll
            for (int off = 1; off < 8; off <<= 1)
                rs += __shfl_xor_sync(0xffffffffu, rs, off);
            l[i] = l[i] * factor + rs;
            #pragma unroll
            for (int j = 0; j < 8; j++) acc[i][j] *= factor;
            #pragma unroll
            for (int j = 0; j < 8; j++)
                Ps[(ty * 4 + i) * PS + j * 8 + tx] = s[i][j];
        }
        __syncthreads();

        #pragma unroll
        for (int j = 0; j < KTILE; j += 4) {
            float pa[4][4];
            #pragma unroll
            for (int i = 0; i < 4; i++)
                *(float4*)&pa[i][0] = *(const float4*)&Ps[(ty * 4 + i) * PS + j];
            #pragma unroll
            for (int jj = 0; jj < 4; jj++) {
                const float4 v0 = *(const float4*)&Vs[(j + jj) * VS + tx * 8];
                const float4 v1 = *(const float4*)&Vs[(j + jj) * VS + tx * 8 + 4];
                #pragma unroll
                for (int i = 0; i < 4; i++) {
                    const float p = pa[i][jj];
                    acc[i][0] = fmaf(p, v0.x, acc[i][0]);
                    acc[i][1] = fmaf(p, v0.y, acc[i][1]);
                    acc[i][2] = fmaf(p, v0.z, acc[i][2]);
                    acc[i][3] = fmaf(p, v0.w, acc[i][3]);
                    acc[i][4] = fmaf(p, v1.x, acc[i][4]);
                    acc[i][5] = fmaf(p, v1.y, acc[i][5]);
                    acc[i][6] = fmaf(p, v1.z, acc[i][6]);
                    acc[i][7] = fmaf(p, v1.w, acc[i][7]);
                }
            }
        }
        __syncthreads();
    }

    #pragma unroll
    for (int i = 0; i < 4; i++) {
        const float invl = 1.0f / l[i];
        const size_t q = (size_t)(b * S_LEN + q0 + ty * 4 + i);
        float* orow = O + q * D_MODEL + h * DK + tx * 8;
        float4 o0, o1;
        o0.x = acc[i][0] * invl; o0.y = acc[i][1] * invl;
        o0.z = acc[i][2] * invl; o0.w = acc[i][3] * invl;
        o1.x = acc[i][4] * invl; o1.y = acc[i][5] * invl;
        o1.z = acc[i][6] * invl; o1.w = acc[i][7] * invl;
        *(float4*)orow = o0;
        *(float4*)(orow + 4) = o1;
    }
}

// ---------------- launch ---------------------------------------------------
extern "C" void kernel_launch(void* const* d_in, const int* in_sizes, int n_in,
                              void* d_out, int out_size)
{
    const float* x   = (const float*)d_in[0];
    const int*   msk = (const int*)  d_in[1];
    const float* wq  = (const float*)d_in[2];
    const float* bq  = (const float*)d_in[3];
    const float* wk  = (const float*)d_in[4];
    const float* bk  = (const float*)d_in[5];
    const float* wv  = (const float*)d_in[6];
    const float* bv  = (const float*)d_in[7];
    const float* wo  = (const float*)d_in[8];
    const float* bo  = (const float*)d_in[9];
    const float* w1  = (const float*)d_in[10];
    const float* b1  = (const float*)d_in[11];
    const float* w2  = (const float*)d_in[12];
    const float* b2  = (const float*)d_in[13];
    const float* l1a = (const float*)d_in[14];
    const float* l1b = (const float*)d_in[15];
    const float* l2a = (const float*)d_in[16];
    const float* l2b = (const float*)d_in[17];
    float* out = (float*)d_out;

    float *xn, *q, *k, *v, *ctx, *h, *xn2, *mid;
    cudaGetSymbolAddress((void**)&xn,  g_xn);
    cudaGetSymbolAddress((void**)&q,   g_q);
    cudaGetSymbolAddress((void**)&k,   g_k);
    cudaGetSymbolAddress((void**)&v,   g_v);
    cudaGetSymbolAddress((void**)&ctx, g_ctx);
    cudaGetSymbolAddress((void**)&h,   g_h);
    cudaGetSymbolAddress((void**)&xn2, g_xn2);
    cudaGetSymbolAddress((void**)&mid, g_mid);

    cudaFuncSetAttribute(attn_kernel,
        cudaFuncAttributeMaxDynamicSharedMemorySize, ATTN_SMEM);

    // 1. ln1
    ln_kernel<<<M_ROWS, 256>>>(x, l1a, l1b, xn);
    // 2. QKV projections (tensor cores, bf16-split)
    mma_gemm<false, false><<<dim3(D_MODEL/128, M_ROWS/128), 256>>>(
        xn, wq, bq, nullptr, q, M_ROWS, D_MODEL, D_MODEL);
    mma_gemm<false, false><<<dim3(D_MODEL/128, M_ROWS/128), 256>>>(
        xn, wk, bk, nullptr, k, M_ROWS, D_MODEL, D_MODEL);
    mma_gemm<false, false><<<dim3(D_MODEL/128, M_ROWS/128), 256>>>(
        xn, wv, bv, nullptr, v, M_ROWS, D_MODEL, D_MODEL);
    // 3. attention
    attn_kernel<<<dim3(S_LEN/QTILE, N_HEADS, B_SZ), 256, ATTN_SMEM>>>(
        q, k, v, msk, ctx);
    // 4. output projection + residual with x
    mma_gemm<false, true><<<dim3(D_MODEL/128, M_ROWS/128), 256>>>(
        ctx, wo, bo, x, h, M_ROWS, D_MODEL, D_MODEL);
    // 5. ln2
    ln_kernel<<<M_ROWS, 256>>>(h, l2a, l2b, xn2);
    // 6. FFN up + relu
    mma_gemm<true, false><<<dim3(F_FFN/128, M_ROWS/128), 256>>>(
        xn2, w1, b1, nullptr, mid, M_ROWS, F_FFN, D_MODEL);
    // 7. FFN down + residual with h -> out
    mma_gemm<false, true><<<dim3(D_MODEL/128, M_ROWS/128), 256>>>(
        mid, w2, b2, h, out, M_ROWS, D_MODEL, F_FFN);
}

// round 6
// speedup vs baseline: 1.9308x; 1.6825x over previous
#include <cuda_runtime.h>
#include <cuda_bf16.h>
#include <math.h>
#include <stdint.h>

#define D_MODEL 1024
#define F_FFN   4096
#define B_SZ    4
#define S_LEN   2048
#define N_HEADS 16
#define DK      64
#define M_ROWS  (B_SZ * S_LEN)   // 8192
#define LN_EPS  1e-6f

// ---------------- scratch (no allocs allowed) ----------------
__device__ float g_xn [(size_t)M_ROWS * D_MODEL];
__device__ float g_q  [(size_t)M_ROWS * D_MODEL];
__device__ float g_k  [(size_t)M_ROWS * D_MODEL];
__device__ float g_v  [(size_t)M_ROWS * D_MODEL];
__device__ float g_ctx[(size_t)M_ROWS * D_MODEL];
__device__ float g_h  [(size_t)M_ROWS * D_MODEL];
__device__ float g_xn2[(size_t)M_ROWS * D_MODEL];
__device__ float g_mid[(size_t)M_ROWS * F_FFN];

// ---------------- LayerNorm (torch semantics: ddof=1, eps added to std) ----
__global__ void __launch_bounds__(256) ln_kernel(
    const float* __restrict__ x,
    const float* __restrict__ alpha,
    const float* __restrict__ beta,
    float* __restrict__ out)
{
    __shared__ float red[32];
    const int row = blockIdx.x;
    const int tid = threadIdx.x;

    const float4 v = ((const float4*)(x + (size_t)row * D_MODEL))[tid];
    float s  = v.x + v.y + v.z + v.w;
    float s2 = v.x * v.x + v.y * v.y + v.z * v.z + v.w * v.w;
    #pragma unroll
    for (int off = 16; off > 0; off >>= 1) {
        s  += __shfl_xor_sync(0xffffffffu, s,  off);
        s2 += __shfl_xor_sync(0xffffffffu, s2, off);
    }
    const int warp = tid >> 5;
    if ((tid & 31) == 0) { red[warp] = s; red[8 + warp] = s2; }
    __syncthreads();
    if (tid == 0) {
        float ts = 0.f, ts2 = 0.f;
        #pragma unroll
        for (int i = 0; i < 8; i++) { ts += red[i]; ts2 += red[8 + i]; }
        const float mean = ts * (1.0f / (float)D_MODEL);
        float var = (ts2 - (float)D_MODEL * mean * mean) * (1.0f / (float)(D_MODEL - 1));
        var = fmaxf(var, 0.0f);
        red[16] = mean;
        red[17] = 1.0f / (sqrtf(var) + LN_EPS);
    }
    __syncthreads();
    const float mean = red[16], inv = red[17];
    const float4 a = ((const float4*)alpha)[tid];
    const float4 b = ((const float4*)beta)[tid];
    float4 o;
    o.x = a.x * (v.x - mean) * inv + b.x;
    o.y = a.y * (v.y - mean) * inv + b.y;
    o.z = a.z * (v.z - mean) * inv + b.z;
    o.w = a.w * (v.w - mean) * inv + b.w;
    ((float4*)(out + (size_t)row * D_MODEL))[tid] = o;
}

// ---------------- common mma helpers ---------------------------------------
__device__ __forceinline__ uint32_t smem_u32(const void* p) {
    return (uint32_t)__cvta_generic_to_shared(p);
}

#define LDSM_X4(r0,r1,r2,r3,addr) \
    asm volatile("ldmatrix.sync.aligned.m8n8.x4.shared.b16 {%0,%1,%2,%3},[%4];" \
        : "=r"(r0), "=r"(r1), "=r"(r2), "=r"(r3) : "r"(addr))

#define LDSM_X4T(r0,r1,r2,r3,addr) \
    asm volatile("ldmatrix.sync.aligned.m8n8.x4.trans.shared.b16 {%0,%1,%2,%3},[%4];" \
        : "=r"(r0), "=r"(r1), "=r"(r2), "=r"(r3) : "r"(addr))

#define MMA16816(c,a,b0,b1) \
    asm volatile("mma.sync.aligned.m16n8k16.row.col.f32.bf16.bf16.f32 " \
        "{%0,%1,%2,%3},{%4,%5,%6,%7},{%8,%9},{%0,%1,%2,%3};" \
        : "+f"((c)[0]), "+f"((c)[1]), "+f"((c)[2]), "+f"((c)[3]) \
        : "r"((a)[0]), "r"((a)[1]), "r"((a)[2]), "r"((a)[3]), "r"(b0), "r"(b1))

__device__ __forceinline__ void split2(float x, __nv_bfloat16& h, __nv_bfloat16& l) {
    h = __float2bfloat16(x);
    l = __float2bfloat16(x - __bfloat162float(h));
}

// pack two floats into bf16x2 hi + bf16x2 lo words
__device__ __forceinline__ void pack_hl(float x, float y, uint32_t& h, uint32_t& l) {
    __nv_bfloat16 hx, lx, hy, ly;
    split2(x, hx, lx);
    split2(y, hy, ly);
    __nv_bfloat162 hp = __halves2bfloat162(hx, hy);
    __nv_bfloat162 lp = __halves2bfloat162(lx, ly);
    h = *(uint32_t*)&hp;
    l = *(uint32_t*)&lp;
}

// ---------------- Tensor-core GEMM via bf16 split -------------------------
// C[M,N] = A[M,K] @ B[K,N] + bias [+res] [relu]
// Block 128x128, K-tile 32, 256 thr = 8 warps (4M x 2N), warp tile 32x64.
#define ASTR 40
#define BSTR 136

template<bool RELU, bool RES>
__global__ void __launch_bounds__(256) mma_gemm(
    const float* __restrict__ A, const float* __restrict__ B,
    const float* __restrict__ bias, const float* __restrict__ res,
    float* __restrict__ C, int M, int N, int K)
{
    __shared__ __nv_bfloat16 As_hi[128 * ASTR];
    __shared__ __nv_bfloat16 As_lo[128 * ASTR];
    __shared__ __nv_bfloat16 Bs_hi[32 * BSTR];
    __shared__ __nv_bfloat16 Bs_lo[32 * BSTR];

    const int tid  = threadIdx.x;
    const int lane = tid & 31;
    const int wid  = tid >> 5;
    const int wm   = (wid & 3) * 32;
    const int wn   = (wid >> 2) * 64;
    const int bx = blockIdx.x, by = blockIdx.y;

    const float* Ab = A + (size_t)(by * 128) * K;
    const float* Bb = B + bx * 128;

    const int a_row = tid >> 1, a_c0 = (tid & 1) * 16;
    const int b_row = tid >> 3, b_c0 = (tid & 7) * 16;

    const int lane16 = lane & 15;
    const int lane8  = (lane >> 4) * 8;
    const uint32_t ash = smem_u32(As_hi), asl = smem_u32(As_lo);
    const uint32_t bsh = smem_u32(Bs_hi), bsl = smem_u32(Bs_lo);
    const uint32_t a_off = ((wm + lane16) * ASTR + lane8) * 2;
    const uint32_t b_off = (lane16 * BSTR + wn + lane8) * 2;

    float acc[2][8][4];
    #pragma unroll
    for (int i = 0; i < 2; i++)
        #pragma unroll
        for (int j = 0; j < 8; j++)
            #pragma unroll
            for (int q = 0; q < 4; q++) acc[i][j][q] = 0.f;

    float4 av[4], bv[4];
    #pragma unroll
    for (int i = 0; i < 4; i++) {
        av[i] = *(const float4*)(Ab + (size_t)a_row * K + a_c0 + i * 4);
        bv[i] = *(const float4*)(Bb + (size_t)b_row * N + b_c0 + i * 4);
    }

    for (int kt = 0; kt < K; kt += 32) {
        __syncthreads();
        {
            __align__(16) __nv_bfloat16 ah8[16], al8[16], bh8[16], bl8[16];
            #pragma unroll
            for (int i = 0; i < 4; i++) {
                split2(av[i].x, ah8[i*4+0], al8[i*4+0]);
                split2(av[i].y, ah8[i*4+1], al8[i*4+1]);
                split2(av[i].z, ah8[i*4+2], al8[i*4+2]);
                split2(av[i].w, ah8[i*4+3], al8[i*4+3]);
                split2(bv[i].x, bh8[i*4+0], bl8[i*4+0]);
                split2(bv[i].y, bh8[i*4+1], bl8[i*4+1]);
                split2(bv[i].z, bh8[i*4+2], bl8[i*4+2]);
                split2(bv[i].w, bh8[i*4+3], bl8[i*4+3]);
            }
            *(uint4*)&As_hi[a_row * ASTR + a_c0]     = *(uint4*)&ah8[0];
            *(uint4*)&As_hi[a_row * ASTR + a_c0 + 8] = *(uint4*)&ah8[8];
            *(uint4*)&As_lo[a_row * ASTR + a_c0]     = *(uint4*)&al8[0];
            *(uint4*)&As_lo[a_row * ASTR + a_c0 + 8] = *(uint4*)&al8[8];
            *(uint4*)&Bs_hi[b_row * BSTR + b_c0]     = *(uint4*)&bh8[0];
            *(uint4*)&Bs_hi[b_row * BSTR + b_c0 + 8] = *(uint4*)&bh8[8];
            *(uint4*)&Bs_lo[b_row * BSTR + b_c0]     = *(uint4*)&bl8[0];
            *(uint4*)&Bs_lo[b_row * BSTR + b_c0 + 8] = *(uint4*)&bl8[8];
        }
        __syncthreads();

        if (kt + 32 < K) {
            #pragma unroll
            for (int i = 0; i < 4; i++) {
                av[i] = *(const float4*)(Ab + (size_t)a_row * K + (kt + 32) + a_c0 + i * 4);
                bv[i] = *(const float4*)(Bb + (size_t)(kt + 32 + b_row) * N + b_c0 + i * 4);
            }
        }

        #pragma unroll
        for (int ks = 0; ks < 2; ks++) {
            uint32_t ah[2][4], al[2][4];
            #pragma unroll
            for (int mf = 0; mf < 2; mf++) {
                const uint32_t ao = a_off + (mf * 16 * ASTR + ks * 16) * 2;
                LDSM_X4(ah[mf][0], ah[mf][1], ah[mf][2], ah[mf][3], ash + ao);
                LDSM_X4(al[mf][0], al[mf][1], al[mf][2], al[mf][3], asl + ao);
            }
            #pragma unroll
            for (int nf2 = 0; nf2 < 4; nf2++) {
                uint32_t bh[4], bl[4];
                const uint32_t bo = b_off + (ks * 16 * BSTR + nf2 * 16) * 2;
                LDSM_X4T(bh[0], bh[1], bh[2], bh[3], bsh + bo);
                LDSM_X4T(bl[0], bl[1], bl[2], bl[3], bsl + bo);
                #pragma unroll
                for (int mf = 0; mf < 2; mf++) {
                    #pragma unroll
                    for (int h = 0; h < 2; h++) {
                        float* c = acc[mf][nf2 * 2 + h];
                        MMA16816(c, ah[mf], bh[2 * h], bh[2 * h + 1]);
                        MMA16816(c, ah[mf], bl[2 * h], bl[2 * h + 1]);
                        MMA16816(c, al[mf], bh[2 * h], bh[2 * h + 1]);
                    }
                }
            }
        }
    }

    const int g = lane >> 2, t = lane & 3;
    #pragma unroll
    for (int mf = 0; mf < 2; mf++) {
        #pragma unroll
        for (int nf = 0; nf < 8; nf++) {
            const int col = bx * 128 + wn + nf * 8 + t * 2;
            const float2 bb = *(const float2*)(bias + col);
            #pragma unroll
            for (int half = 0; half < 2; half++) {
                const size_t r = (size_t)(by * 128 + wm + mf * 16 + g + half * 8);
                float2 o;
                o.x = acc[mf][nf][half * 2 + 0] + bb.x;
                o.y = acc[mf][nf][half * 2 + 1] + bb.y;
                if (RES) {
                    const float2 rv = *(const float2*)(res + r * N + col);
                    o.x += rv.x; o.y += rv.y;
                }
                if (RELU) { o.x = fmaxf(o.x, 0.f); o.y = fmaxf(o.y, 0.f); }
                *(float2*)(C + r * N + col) = o;
            }
        }
    }
}

// ---------------- Tensor-core flash attention -------------------------------
// Block: 256 threads (8 warps), 128 q-rows (16 per warp), K-tile 64, dk=64.
// bf16 split (3-term) for both QK^T and P.V. Softmax entirely in registers.
#define AQS 72   // smem row stride (bf16 elems); 144B rows -> conflict-free ldmatrix
#define ATTN_SMEM_B ((128*2 + 64*4) * AQS * 2 + 64 * 4)

__global__ void __launch_bounds__(256) attn_mma(
    const float* __restrict__ Q, const float* __restrict__ K,
    const float* __restrict__ V, const int* __restrict__ mask,
    float* __restrict__ O)
{
    extern __shared__ char smraw[];
    __nv_bfloat16* Qh = (__nv_bfloat16*)smraw;
    __nv_bfloat16* Ql = Qh + 128 * AQS;
    __nv_bfloat16* Kh = Ql + 128 * AQS;
    __nv_bfloat16* Kl = Kh + 64 * AQS;
    __nv_bfloat16* Vh = Kl + 64 * AQS;
    __nv_bfloat16* Vl = Vh + 64 * AQS;
    float* Ms = (float*)(Vl + 64 * AQS);

    const int b  = blockIdx.z;
    const int h  = blockIdx.y;
    const int q0 = blockIdx.x * 128;
    const int tid  = threadIdx.x;
    const int lane = tid & 31;
    const int wid  = tid >> 5;
    const int lane16 = lane & 15;
    const int lane8  = (lane >> 4) * 8;
    const int g  = lane >> 2;
    const int t2 = (lane & 3) * 2;

    const uint32_t qsh = smem_u32(Qh), qsl = smem_u32(Ql);
    const uint32_t ksh = smem_u32(Kh), ksl = smem_u32(Kl);
    const uint32_t vsh = smem_u32(Vh), vsl = smem_u32(Vl);

    // ---- stage Q tile (128 x 64) as bf16 hi/lo ----
    {
        const int r  = tid >> 1;
        const int c0 = (tid & 1) * 32;
        const float* qp = Q + ((size_t)(b * S_LEN + q0 + r)) * D_MODEL + h * DK + c0;
        __align__(16) __nv_bfloat16 hb[32], lb[32];
        #pragma unroll
        for (int i = 0; i < 8; i++) {
            const float4 f = ((const float4*)qp)[i];
            split2(f.x, hb[i*4+0], lb[i*4+0]);
            split2(f.y, hb[i*4+1], lb[i*4+1]);
            split2(f.z, hb[i*4+2], lb[i*4+2]);
            split2(f.w, hb[i*4+3], lb[i*4+3]);
        }
        #pragma unroll
        for (int i = 0; i < 4; i++) {
            *(uint4*)&Qh[r * AQS + c0 + i * 8] = *(uint4*)&hb[i * 8];
            *(uint4*)&Ql[r * AQS + c0 + i * 8] = *(uint4*)&lb[i * 8];
        }
    }
    __syncthreads();

    // ---- preload Q fragments (constant across k-tiles) ----
    uint32_t qfh[4][4], qfl[4][4];
    #pragma unroll
    for (int kc = 0; kc < 4; kc++) {
        const uint32_t ao = ((wid * 16 + lane16) * AQS + kc * 16 + lane8) * 2;
        LDSM_X4(qfh[kc][0], qfh[kc][1], qfh[kc][2], qfh[kc][3], qsh + ao);
        LDSM_X4(qfl[kc][0], qfl[kc][1], qfl[kc][2], qfl[kc][3], qsl + ao);
    }

    float accO[8][4];
    #pragma unroll
    for (int j = 0; j < 8; j++)
        #pragma unroll
        for (int q = 0; q < 4; q++) accO[j][q] = 0.f;
    float mrow[2] = {-1e30f, -1e30f};
    float lrow[2] = {0.f, 0.f};

    const int kv_r = tid >> 2;            // 0..63
    const int kv_c = (tid & 3) * 16;      // 0,16,32,48

    for (int kt = 0; kt < S_LEN; kt += 64) {
        __syncthreads();
        // ---- stage K,V tiles (64 x 64 each) ----
        {
            const size_t roff = ((size_t)(b * S_LEN + kt + kv_r)) * D_MODEL + h * DK + kv_c;
            const float* kp = K + roff;
            const float* vp = V + roff;
            __align__(16) __nv_bfloat16 khb[16], klb[16], vhb[16], vlb[16];
            #pragma unroll
            for (int i = 0; i < 4; i++) {
                const float4 fk = ((const float4*)kp)[i];
                const float4 fv = ((const float4*)vp)[i];
                split2(fk.x, khb[i*4+0], klb[i*4+0]);
                split2(fk.y, khb[i*4+1], klb[i*4+1]);
                split2(fk.z, khb[i*4+2], klb[i*4+2]);
                split2(fk.w, khb[i*4+3], klb[i*4+3]);
                split2(fv.x, vhb[i*4+0], vlb[i*4+0]);
                split2(fv.y, vhb[i*4+1], vlb[i*4+1]);
                split2(fv.z, vhb[i*4+2], vlb[i*4+2]);
                split2(fv.w, vhb[i*4+3], vlb[i*4+3]);
            }
            *(uint4*)&Kh[kv_r * AQS + kv_c]     = *(uint4*)&khb[0];
            *(uint4*)&Kh[kv_r * AQS + kv_c + 8] = *(uint4*)&khb[8];
            *(uint4*)&Kl[kv_r * AQS + kv_c]     = *(uint4*)&klb[0];
            *(uint4*)&Kl[kv_r * AQS + kv_c + 8] = *(uint4*)&klb[8];
            *(uint4*)&Vh[kv_r * AQS + kv_c]     = *(uint4*)&vhb[0];
            *(uint4*)&Vh[kv_r * AQS + kv_c + 8] = *(uint4*)&vhb[8];
            *(uint4*)&Vl[kv_r * AQS + kv_c]     = *(uint4*)&vlb[0];
            *(uint4*)&Vl[kv_r * AQS + kv_c + 8] = *(uint4*)&vlb[8];
        }
        if (tid < 64)
            Ms[tid] = (mask[b * S_LEN + kt + tid] == 0) ? -1e9f : 0.f;
        __syncthreads();

        // ---- S = Q K^T : per-warp 16 x 64 (8 n-tiles) ----
        float sc[8][4];
        #pragma unroll
        for (int j = 0; j < 8; j++)
            #pragma unroll
            for (int q = 0; q < 4; q++) sc[j][q] = 0.f;

        #pragma unroll
        for (int np = 0; np < 4; np++) {
            uint32_t kh[4][4], kl[4][4];
            #pragma unroll
            for (int kc = 0; kc < 4; kc++) {
                const uint32_t ko = ((np * 16 + lane16) * AQS + kc * 16 + lane8) * 2;
                LDSM_X4(kh[kc][0], kh[kc][1], kh[kc][2], kh[kc][3], ksh + ko);
                LDSM_X4(kl[kc][0], kl[kc][1], kl[kc][2], kl[kc][3], ksl + ko);
            }
            #pragma unroll
            for (int kc = 0; kc < 4; kc++) {
                MMA16816(sc[2*np],   qfh[kc], kh[kc][0], kh[kc][2]);
                MMA16816(sc[2*np],   qfh[kc], kl[kc][0], kl[kc][2]);
                MMA16816(sc[2*np],   qfl[kc], kh[kc][0], kh[kc][2]);
                MMA16816(sc[2*np+1], qfh[kc], kh[kc][1], kh[kc][3]);
                MMA16816(sc[2*np+1], qfh[kc], kl[kc][1], kl[kc][3]);
                MMA16816(sc[2*np+1], qfl[kc], kh[kc][1], kh[kc][3]);
            }
        }

        // ---- online softmax (registers + quad shuffles) ----
        #pragma unroll
        for (int r = 0; r < 2; r++) {
            float mx = -1e30f;
            #pragma unroll
            for (int j = 0; j < 8; j++) {
                sc[j][2*r]   = sc[j][2*r]   * 0.125f + Ms[j * 8 + t2];
                sc[j][2*r+1] = sc[j][2*r+1] * 0.125f + Ms[j * 8 + t2 + 1];
                mx = fmaxf(mx, fmaxf(sc[j][2*r], sc[j][2*r+1]));
            }
            mx = fmaxf(mx, __shfl_xor_sync(0xffffffffu, mx, 1));
            mx = fmaxf(mx, __shfl_xor_sync(0xffffffffu, mx, 2));
            const float nm = fmaxf(mrow[r], mx);
            const float f  = __expf(mrow[r] - nm);
            mrow[r] = nm;
            float sum = 0.f;
            #pragma unroll
            for (int j = 0; j < 8; j++) {
                sc[j][2*r]   = __expf(sc[j][2*r]   - nm);
                sc[j][2*r+1] = __expf(sc[j][2*r+1] - nm);
                sum += sc[j][2*r] + sc[j][2*r+1];
            }
            sum += __shfl_xor_sync(0xffffffffu, sum, 1);
            sum += __shfl_xor_sync(0xffffffffu, sum, 2);
            lrow[r] = lrow[r] * f + sum;
            #pragma unroll
            for (int j = 0; j < 8; j++) {
                accO[j][2*r]   *= f;
                accO[j][2*r+1] *= f;
            }
        }

        // ---- O += P @ V (P fragments direct from S accumulators) ----
        #pragma unroll
        for (int kc = 0; kc < 4; kc++) {
            uint32_t pah[4], pal[4];
            pack_hl(sc[2*kc][0],   sc[2*kc][1],   pah[0], pal[0]);
            pack_hl(sc[2*kc][2],   sc[2*kc][3],   pah[1], pal[1]);
            pack_hl(sc[2*kc+1][0], sc[2*kc+1][1], pah[2], pal[2]);
            pack_hl(sc[2*kc+1][2], sc[2*kc+1][3], pah[3], pal[3]);
            #pragma unroll
            for (int nd = 0; nd < 4; nd++) {
                uint32_t vh[4], vl[4];
                const uint32_t vo = ((kc * 16 + lane16) * AQS + nd * 16 + lane8) * 2;
                LDSM_X4T(vh[0], vh[1], vh[2], vh[3], vsh + vo);
                LDSM_X4T(vl[0], vl[1], vl[2], vl[3], vsl + vo);
                MMA16816(accO[nd*2],   pah, vh[0], vh[1]);
                MMA16816(accO[nd*2],   pah, vl[0], vl[1]);
                MMA16816(accO[nd*2],   pal, vh[0], vh[1]);
                MMA16816(accO[nd*2+1], pah, vh[2], vh[3]);
                MMA16816(accO[nd*2+1], pah, vl[2], vl[3]);
                MMA16816(accO[nd*2+1], pal, vh[2], vh[3]);
            }
        }
    }

    // ---- epilogue: ctx[b, q, h*64 + col] = accO / l ----
    #pragma unroll
    for (int r = 0; r < 2; r++) {
        const float inv = 1.0f / lrow[r];
        const int qrow = q0 + wid * 16 + g + r * 8;
        float* op = O + ((size_t)(b * S_LEN + qrow)) * D_MODEL + h * DK + t2;
        #pragma unroll
        for (int j = 0; j < 8; j++) {
            float2 o;
            o.x = accO[j][2*r]   * inv;
            o.y = accO[j][2*r+1] * inv;
            *(float2*)(op + j * 8) = o;
        }
    }
}

// ---------------- launch ---------------------------------------------------
extern "C" void kernel_launch(void* const* d_in, const int* in_sizes, int n_in,
                              void* d_out, int out_size)
{
    const float* x   = (const float*)d_in[0];
    const int*   msk = (const int*)  d_in[1];
    const float* wq  = (const float*)d_in[2];
    const float* bq  = (const float*)d_in[3];
    const float* wk  = (const float*)d_in[4];
    const float* bk  = (const float*)d_in[5];
    const float* wv  = (const float*)d_in[6];
    const float* bv  = (const float*)d_in[7];
    const float* wo  = (const float*)d_in[8];
    const float* bo  = (const float*)d_in[9];
    const float* w1  = (const float*)d_in[10];
    const float* b1  = (const float*)d_in[11];
    const float* w2  = (const float*)d_in[12];
    const float* b2  = (const float*)d_in[13];
    const float* l1a = (const float*)d_in[14];
    const float* l1b = (const float*)d_in[15];
    const float* l2a = (const float*)d_in[16];
    const float* l2b = (const float*)d_in[17];
    float* out = (float*)d_out;

    float *xn, *q, *k, *v, *ctx, *h, *xn2, *mid;
    cudaGetSymbolAddress((void**)&xn,  g_xn);
    cudaGetSymbolAddress((void**)&q,   g_q);
    cudaGetSymbolAddress((void**)&k,   g_k);
    cudaGetSymbolAddress((void**)&v,   g_v);
    cudaGetSymbolAddress((void**)&ctx, g_ctx);
    cudaGetSymbolAddress((void**)&h,   g_h);
    cudaGetSymbolAddress((void**)&xn2, g_xn2);
    cudaGetSymbolAddress((void**)&mid, g_mid);

    cudaFuncSetAttribute(attn_mma,
        cudaFuncAttributeMaxDynamicSharedMemorySize, ATTN_SMEM_B);

    // 1. ln1
    ln_kernel<<<M_ROWS, 256>>>(x, l1a, l1b, xn);
    // 2. QKV projections
    mma_gemm<false, false><<<dim3(D_MODEL/128, M_ROWS/128), 256>>>(
        xn, wq, bq, nullptr, q, M_ROWS, D_MODEL, D_MODEL);
    mma_gemm<false, false><<<dim3(D_MODEL/128, M_ROWS/128), 256>>>(
        xn, wk, bk, nullptr, k, M_ROWS, D_MODEL, D_MODEL);
    mma_gemm<false, false><<<dim3(D_MODEL/128, M_ROWS/128), 256>>>(
        xn, wv, bv, nullptr, v, M_ROWS, D_MODEL, D_MODEL);
    // 3. attention (tensor cores)
    attn_mma<<<dim3(S_LEN/128, N_HEADS, B_SZ), 256, ATTN_SMEM_B>>>(
        q, k, v, msk, ctx);
    // 4. output projection + residual with x
    mma_gemm<false, true><<<dim3(D_MODEL/128, M_ROWS/128), 256>>>(
        ctx, wo, bo, x, h, M_ROWS, D_MODEL, D_MODEL);
    // 5. ln2
    ln_kernel<<<M_ROWS, 256>>>(h, l2a, l2b, xn2);
    // 6. FFN up + relu
    mma_gemm<true, false><<<dim3(F_FFN/128, M_ROWS/128), 256>>>(
        xn2, w1, b1, nullptr, mid, M_ROWS, F_FFN, D_MODEL);
    // 7. FFN down + residual with h -> out
    mma_gemm<false, true><<<dim3(D_MODEL/128, M_ROWS/128), 256>>>(
        mid, w2, b2, h, out, M_ROWS, D_MODEL, F_FFN);
}

// round 7
// speedup vs baseline: 2.2731x; 1.1773x over previous
#include <cuda_runtime.h>
#include <cuda_bf16.h>
#include <math.h>
#include <stdint.h>

#define D_MODEL 1024
#define F_FFN   4096
#define B_SZ    4
#define S_LEN   2048
#define N_HEADS 16
#define DK      64
#define M_ROWS  (B_SZ * S_LEN)   // 8192
#define LN_EPS  1e-6f

typedef __nv_bfloat16 bf16;

// ---------------- scratch (no allocs allowed) ----------------
// activations as pre-split bf16 hi/lo
__device__ bf16 g_xn_h [(size_t)M_ROWS * D_MODEL];
__device__ bf16 g_xn_l [(size_t)M_ROWS * D_MODEL];
__device__ bf16 g_q_h  [(size_t)M_ROWS * D_MODEL];
__device__ bf16 g_q_l  [(size_t)M_ROWS * D_MODEL];
__device__ bf16 g_k_h  [(size_t)M_ROWS * D_MODEL];
__device__ bf16 g_k_l  [(size_t)M_ROWS * D_MODEL];
__device__ bf16 g_v_h  [(size_t)M_ROWS * D_MODEL];
__device__ bf16 g_v_l  [(size_t)M_ROWS * D_MODEL];
__device__ bf16 g_ctx_h[(size_t)M_ROWS * D_MODEL];
__device__ bf16 g_ctx_l[(size_t)M_ROWS * D_MODEL];
__device__ float g_hbuf[(size_t)M_ROWS * D_MODEL];
__device__ bf16 g_xn2_h[(size_t)M_ROWS * D_MODEL];
__device__ bf16 g_xn2_l[(size_t)M_ROWS * D_MODEL];
__device__ bf16 g_mid_h[(size_t)M_ROWS * F_FFN];
__device__ bf16 g_mid_l[(size_t)M_ROWS * F_FFN];
// weights pre-split
__device__ bf16 g_wq_h[(size_t)D_MODEL * D_MODEL];
__device__ bf16 g_wq_l[(size_t)D_MODEL * D_MODEL];
__device__ bf16 g_wk_h[(size_t)D_MODEL * D_MODEL];
__device__ bf16 g_wk_l[(size_t)D_MODEL * D_MODEL];
__device__ bf16 g_wv_h[(size_t)D_MODEL * D_MODEL];
__device__ bf16 g_wv_l[(size_t)D_MODEL * D_MODEL];
__device__ bf16 g_wo_h[(size_t)D_MODEL * D_MODEL];
__device__ bf16 g_wo_l[(size_t)D_MODEL * D_MODEL];
__device__ bf16 g_w1_h[(size_t)D_MODEL * F_FFN];
__device__ bf16 g_w1_l[(size_t)D_MODEL * F_FFN];
__device__ bf16 g_w2_h[(size_t)F_FFN * D_MODEL];
__device__ bf16 g_w2_l[(size_t)F_FFN * D_MODEL];

// ---------------- helpers ---------------------------------------------------
__device__ __forceinline__ uint32_t smem_u32(const void* p) {
    return (uint32_t)__cvta_generic_to_shared(p);
}

#define LDSM_X4(r0,r1,r2,r3,addr) \
    asm volatile("ldmatrix.sync.aligned.m8n8.x4.shared.b16 {%0,%1,%2,%3},[%4];" \
        : "=r"(r0), "=r"(r1), "=r"(r2), "=r"(r3) : "r"(addr))

#define LDSM_X4T(r0,r1,r2,r3,addr) \
    asm volatile("ldmatrix.sync.aligned.m8n8.x4.trans.shared.b16 {%0,%1,%2,%3},[%4];" \
        : "=r"(r0), "=r"(r1), "=r"(r2), "=r"(r3) : "r"(addr))

#define MMA16816(c,a,b0,b1) \
    asm volatile("mma.sync.aligned.m16n8k16.row.col.f32.bf16.bf16.f32 " \
        "{%0,%1,%2,%3},{%4,%5,%6,%7},{%8,%9},{%0,%1,%2,%3};" \
        : "+f"((c)[0]), "+f"((c)[1]), "+f"((c)[2]), "+f"((c)[3]) \
        : "r"((a)[0]), "r"((a)[1]), "r"((a)[2]), "r"((a)[3]), "r"(b0), "r"(b1))

#define CP16(dst, src) \
    asm volatile("cp.async.cg.shared.global [%0],[%1],16;" :: "r"(dst), "l"(src))
#define CP_COMMIT asm volatile("cp.async.commit_group;")

__device__ __forceinline__ void split2(float x, bf16& h, bf16& l) {
    h = __float2bfloat16(x);
    l = __float2bfloat16(x - __bfloat162float(h));
}

__device__ __forceinline__ void pack_hl(float x, float y, uint32_t& h, uint32_t& l) {
    bf16 hx, lx, hy, ly;
    split2(x, hx, lx);
    split2(y, hy, ly);
    __nv_bfloat162 hp = __halves2bfloat162(hx, hy);
    __nv_bfloat162 lp = __halves2bfloat162(lx, ly);
    h = *(uint32_t*)&hp;
    l = *(uint32_t*)&lp;
}

// ---------------- fp32 -> bf16 hi/lo split ----------------------------------
__global__ void __launch_bounds__(256) split_kernel(
    const float* __restrict__ in, bf16* __restrict__ oh, bf16* __restrict__ ol)
{
    const size_t i = ((size_t)blockIdx.x * 256 + threadIdx.x) * 4;
    const float4 f = *(const float4*)(in + i);
    __align__(8) bf16 h4[4], l4[4];
    split2(f.x, h4[0], l4[0]);
    split2(f.y, h4[1], l4[1]);
    split2(f.z, h4[2], l4[2]);
    split2(f.w, h4[3], l4[3]);
    *(uint2*)(oh + i) = *(uint2*)h4;
    *(uint2*)(ol + i) = *(uint2*)l4;
}

// ---------------- LayerNorm -> bf16 hi/lo -----------------------------------
__global__ void __launch_bounds__(256) ln_split_kernel(
    const float* __restrict__ x,
    const float* __restrict__ alpha,
    const float* __restrict__ beta,
    bf16* __restrict__ oh, bf16* __restrict__ ol)
{
    __shared__ float red[32];
    const int row = blockIdx.x;
    const int tid = threadIdx.x;

    const float4 v = ((const float4*)(x + (size_t)row * D_MODEL))[tid];
    float s  = v.x + v.y + v.z + v.w;
    float s2 = v.x * v.x + v.y * v.y + v.z * v.z + v.w * v.w;
    #pragma unroll
    for (int off = 16; off > 0; off >>= 1) {
        s  += __shfl_xor_sync(0xffffffffu, s,  off);
        s2 += __shfl_xor_sync(0xffffffffu, s2, off);
    }
    const int warp = tid >> 5;
    if ((tid & 31) == 0) { red[warp] = s; red[8 + warp] = s2; }
    __syncthreads();
    if (tid == 0) {
        float ts = 0.f, ts2 = 0.f;
        #pragma unroll
        for (int i = 0; i < 8; i++) { ts += red[i]; ts2 += red[8 + i]; }
        const float mean = ts * (1.0f / (float)D_MODEL);
        float var = (ts2 - (float)D_MODEL * mean * mean) * (1.0f / (float)(D_MODEL - 1));
        var = fmaxf(var, 0.0f);
        red[16] = mean;
        red[17] = 1.0f / (sqrtf(var) + LN_EPS);
    }
    __syncthreads();
    const float mean = red[16], inv = red[17];
    const float4 a = ((const float4*)alpha)[tid];
    const float4 b = ((const float4*)beta)[tid];
    __align__(8) bf16 h4[4], l4[4];
    split2(a.x * (v.x - mean) * inv + b.x, h4[0], l4[0]);
    split2(a.y * (v.y - mean) * inv + b.y, h4[1], l4[1]);
    split2(a.z * (v.z - mean) * inv + b.z, h4[2], l4[2]);
    split2(a.w * (v.w - mean) * inv + b.w, h4[3], l4[3]);
    *(uint2*)(oh + (size_t)row * D_MODEL + tid * 4) = *(uint2*)h4;
    *(uint2*)(ol + (size_t)row * D_MODEL + tid * 4) = *(uint2*)l4;
}

// ---------------- Tensor-core GEMM, pre-split bf16 inputs -------------------
// C = A @ B + bias [+res][relu]; A,B given as hi/lo bf16.
// Block 128x128, K-tile 32, 2-stage cp.async pipeline.
// 256 thr = 8 warps (4M x 2N), warp tile 32x64, 3-term split product.
#define ASTR 40
#define BSTR 136
#define STAGE_A (128 * ASTR)
#define STAGE_B (32 * BSTR)
#define STAGE_ELEMS (2 * STAGE_A + 2 * STAGE_B)
#define GEMM_SMEM (2 * STAGE_ELEMS * 2)

template<bool RELU, bool RES, bool BF16OUT>
__global__ void __launch_bounds__(256) mma_gemm(
    const bf16* __restrict__ Ah, const bf16* __restrict__ Al,
    const bf16* __restrict__ Bh, const bf16* __restrict__ Bl,
    const float* __restrict__ bias, const float* __restrict__ res,
    float* __restrict__ C, bf16* __restrict__ Ch, bf16* __restrict__ Cl,
    int M, int N, int K)
{
    extern __shared__ bf16 sm[];
    const int tid  = threadIdx.x;
    const int lane = tid & 31;
    const int wid  = tid >> 5;
    const int wm   = (wid & 3) * 32;
    const int wn   = (wid >> 2) * 64;
    const int bx = blockIdx.x, by = blockIdx.y;

    const bf16* Abh = Ah + (size_t)(by * 128) * K;
    const bf16* Abl = Al + (size_t)(by * 128) * K;
    const bf16* Bbh = Bh + bx * 128;
    const bf16* Bbl = Bl + bx * 128;

    const int a_row = tid >> 1, a_c = (tid & 1) * 16;
    const int b_row = tid >> 3, b_c = (tid & 7) * 16;

    const uint32_t s_base = smem_u32(sm);
    const uint32_t a_dst = s_base + (uint32_t)(a_row * ASTR + a_c) * 2;
    const uint32_t b_dst = s_base + (uint32_t)(2 * STAGE_A + b_row * BSTR + b_c) * 2;

    const int lane16 = lane & 15;
    const int lane8  = (lane >> 4) * 8;
    const uint32_t a_off = (uint32_t)(((wm + lane16) * ASTR + lane8) * 2);
    const uint32_t b_off = (uint32_t)((lane16 * BSTR + wn + lane8) * 2);

    float acc[2][8][4];
    #pragma unroll
    for (int i = 0; i < 2; i++)
        #pragma unroll
        for (int j = 0; j < 8; j++)
            #pragma unroll
            for (int q = 0; q < 4; q++) acc[i][j][q] = 0.f;

    const int NT = K >> 5;

    // prefetch stage 0
    {
        const uint32_t so = 0;
        CP16(a_dst + so, Abh + (size_t)a_row * K + a_c);
        CP16(a_dst + so + 16, Abh + (size_t)a_row * K + a_c + 8);
        CP16(a_dst + so + STAGE_A * 2, Abl + (size_t)a_row * K + a_c);
        CP16(a_dst + so + STAGE_A * 2 + 16, Abl + (size_t)a_row * K + a_c + 8);
        CP16(b_dst + so, Bbh + (size_t)b_row * N + b_c);
        CP16(b_dst + so + 16, Bbh + (size_t)b_row * N + b_c + 8);
        CP16(b_dst + so + STAGE_B * 2, Bbl + (size_t)b_row * N + b_c);
        CP16(b_dst + so + STAGE_B * 2 + 16, Bbl + (size_t)b_row * N + b_c + 8);
        CP_COMMIT;
    }

    for (int t = 0; t < NT; t++) {
        if (t + 1 < NT) {
            const uint32_t so = (uint32_t)(((t + 1) & 1) * STAGE_ELEMS * 2);
            const int kt = (t + 1) * 32;
            CP16(a_dst + so, Abh + (size_t)a_row * K + kt + a_c);
            CP16(a_dst + so + 16, Abh + (size_t)a_row * K + kt + a_c + 8);
            CP16(a_dst + so + STAGE_A * 2, Abl + (size_t)a_row * K + kt + a_c);
            CP16(a_dst + so + STAGE_A * 2 + 16, Abl + (size_t)a_row * K + kt + a_c + 8);
            CP16(b_dst + so, Bbh + (size_t)(kt + b_row) * N + b_c);
            CP16(b_dst + so + 16, Bbh + (size_t)(kt + b_row) * N + b_c + 8);
            CP16(b_dst + so + STAGE_B * 2, Bbl + (size_t)(kt + b_row) * N + b_c);
            CP16(b_dst + so + STAGE_B * 2 + 16, Bbl + (size_t)(kt + b_row) * N + b_c + 8);
            CP_COMMIT;
            asm volatile("cp.async.wait_group 1;");
        } else {
            asm volatile("cp.async.wait_group 0;");
        }
        __syncthreads();

        const uint32_t so = (uint32_t)((t & 1) * STAGE_ELEMS * 2);
        const uint32_t ash = s_base + so;
        const uint32_t asl = ash + STAGE_A * 2;
        const uint32_t bsh = asl + STAGE_A * 2;
        const uint32_t bsl = bsh + STAGE_B * 2;

        #pragma unroll
        for (int ks = 0; ks < 2; ks++) {
            uint32_t ahf[2][4], alf[2][4];
            #pragma unroll
            for (int mf = 0; mf < 2; mf++) {
                const uint32_t ao = a_off + (uint32_t)((mf * 16 * ASTR + ks * 16) * 2);
                LDSM_X4(ahf[mf][0], ahf[mf][1], ahf[mf][2], ahf[mf][3], ash + ao);
                LDSM_X4(alf[mf][0], alf[mf][1], alf[mf][2], alf[mf][3], asl + ao);
            }
            #pragma unroll
            for (int nf2 = 0; nf2 < 4; nf2++) {
                uint32_t bh[4], bl[4];
                const uint32_t bo = b_off + (uint32_t)((ks * 16 * BSTR + nf2 * 16) * 2);
                LDSM_X4T(bh[0], bh[1], bh[2], bh[3], bsh + bo);
                LDSM_X4T(bl[0], bl[1], bl[2], bl[3], bsl + bo);
                #pragma unroll
                for (int mf = 0; mf < 2; mf++) {
                    #pragma unroll
                    for (int hh = 0; hh < 2; hh++) {
                        float* c = acc[mf][nf2 * 2 + hh];
                        MMA16816(c, ahf[mf], bh[2 * hh], bh[2 * hh + 1]);
                        MMA16816(c, ahf[mf], bl[2 * hh], bl[2 * hh + 1]);
                        MMA16816(c, alf[mf], bh[2 * hh], bh[2 * hh + 1]);
                    }
                }
            }
        }
        __syncthreads();
    }

    const int g = lane >> 2, t4 = lane & 3;
    #pragma unroll
    for (int mf = 0; mf < 2; mf++) {
        #pragma unroll
        for (int nf = 0; nf < 8; nf++) {
            const int col = bx * 128 + wn + nf * 8 + t4 * 2;
            const float2 bb = *(const float2*)(bias + col);
            #pragma unroll
            for (int half = 0; half < 2; half++) {
                const size_t r = (size_t)(by * 128 + wm + mf * 16 + g + half * 8);
                float2 o;
                o.x = acc[mf][nf][half * 2 + 0] + bb.x;
                o.y = acc[mf][nf][half * 2 + 1] + bb.y;
                if (RES) {
                    const float2 rv = *(const float2*)(res + r * N + col);
                    o.x += rv.x; o.y += rv.y;
                }
                if (RELU) { o.x = fmaxf(o.x, 0.f); o.y = fmaxf(o.y, 0.f); }
                if (BF16OUT) {
                    uint32_t hw, lw;
                    pack_hl(o.x, o.y, hw, lw);
                    *(uint32_t*)(Ch + r * N + col) = hw;
                    *(uint32_t*)(Cl + r * N + col) = lw;
                } else {
                    *(float2*)(C + r * N + col) = o;
                }
            }
        }
    }
}

// ---------------- Tensor-core flash attention (pre-split bf16 Q/K/V) --------
#define AQS 72
#define ATTN_SMEM_B ((128*2 + 64*4) * AQS * 2 + 64 * 4)

__global__ void __launch_bounds__(256) attn_mma(
    const bf16* __restrict__ Qh, const bf16* __restrict__ Ql,
    const bf16* __restrict__ Kh, const bf16* __restrict__ Kl,
    const bf16* __restrict__ Vh, const bf16* __restrict__ Vl,
    const int* __restrict__ mask,
    bf16* __restrict__ Oh, bf16* __restrict__ Ol)
{
    extern __shared__ char smraw[];
    bf16* Qhs = (bf16*)smraw;
    bf16* Qls = Qhs + 128 * AQS;
    bf16* Khs = Qls + 128 * AQS;
    bf16* Kls = Khs + 64 * AQS;
    bf16* Vhs = Kls + 64 * AQS;
    bf16* Vls = Vhs + 64 * AQS;
    float* Ms = (float*)(Vls + 64 * AQS);

    const int b  = blockIdx.z;
    const int h  = blockIdx.y;
    const int q0 = blockIdx.x * 128;
    const int tid  = threadIdx.x;
    const int lane = tid & 31;
    const int wid  = tid >> 5;
    const int lane16 = lane & 15;
    const int lane8  = (lane >> 4) * 8;
    const int g  = lane >> 2;
    const int t2 = (lane & 3) * 2;

    const uint32_t qsh = smem_u32(Qhs), qsl = smem_u32(Qls);
    const uint32_t ksh = smem_u32(Khs), ksl = smem_u32(Kls);
    const uint32_t vsh = smem_u32(Vhs), vsl = smem_u32(Vls);

    // ---- stage Q tile (128 x 64) : plain bf16 copies ----
    {
        const int r  = tid >> 1;
        const int c0 = (tid & 1) * 32;
        const size_t go = ((size_t)(b * S_LEN + q0 + r)) * D_MODEL + h * DK + c0;
        #pragma unroll
        for (int i = 0; i < 4; i++) {
            *(uint4*)&Qhs[r * AQS + c0 + i * 8] = *(const uint4*)(Qh + go + i * 8);
            *(uint4*)&Qls[r * AQS + c0 + i * 8] = *(const uint4*)(Ql + go + i * 8);
        }
    }
    __syncthreads();

    // ---- preload Q fragments ----
    uint32_t qfh[4][4], qfl[4][4];
    #pragma unroll
    for (int kc = 0; kc < 4; kc++) {
        const uint32_t ao = ((wid * 16 + lane16) * AQS + kc * 16 + lane8) * 2;
        LDSM_X4(qfh[kc][0], qfh[kc][1], qfh[kc][2], qfh[kc][3], qsh + ao);
        LDSM_X4(qfl[kc][0], qfl[kc][1], qfl[kc][2], qfl[kc][3], qsl + ao);
    }

    float accO[8][4];
    #pragma unroll
    for (int j = 0; j < 8; j++)
        #pragma unroll
        for (int q = 0; q < 4; q++) accO[j][q] = 0.f;
    float mrow[2] = {-1e30f, -1e30f};
    float lrow[2] = {0.f, 0.f};

    const int kv_r = tid >> 2;
    const int kv_c = (tid & 3) * 16;

    for (int kt = 0; kt < S_LEN; kt += 64) {
        __syncthreads();
        {
            const size_t go = ((size_t)(b * S_LEN + kt + kv_r)) * D_MODEL + h * DK + kv_c;
            #pragma unroll
            for (int i = 0; i < 2; i++) {
                *(uint4*)&Khs[kv_r * AQS + kv_c + i * 8] = *(const uint4*)(Kh + go + i * 8);
                *(uint4*)&Kls[kv_r * AQS + kv_c + i * 8] = *(const uint4*)(Kl + go + i * 8);
                *(uint4*)&Vhs[kv_r * AQS + kv_c + i * 8] = *(const uint4*)(Vh + go + i * 8);
                *(uint4*)&Vls[kv_r * AQS + kv_c + i * 8] = *(const uint4*)(Vl + go + i * 8);
            }
        }
        if (tid < 64)
            Ms[tid] = (mask[b * S_LEN + kt + tid] == 0) ? -1e9f : 0.f;
        __syncthreads();

        // ---- S = Q K^T ----
        float sc[8][4];
        #pragma unroll
        for (int j = 0; j < 8; j++)
            #pragma unroll
            for (int q = 0; q < 4; q++) sc[j][q] = 0.f;

        #pragma unroll
        for (int np = 0; np < 4; np++) {
            uint32_t kh[4][4], kl[4][4];
            #pragma unroll
            for (int kc = 0; kc < 4; kc++) {
                const uint32_t ko = ((np * 16 + lane16) * AQS + kc * 16 + lane8) * 2;
                LDSM_X4(kh[kc][0], kh[kc][1], kh[kc][2], kh[kc][3], ksh + ko);
                LDSM_X4(kl[kc][0], kl[kc][1], kl[kc][2], kl[kc][3], ksl + ko);
            }
            #pragma unroll
            for (int kc = 0; kc < 4; kc++) {
                MMA16816(sc[2*np],   qfh[kc], kh[kc][0], kh[kc][2]);
                MMA16816(sc[2*np],   qfh[kc], kl[kc][0], kl[kc][2]);
                MMA16816(sc[2*np],   qfl[kc], kh[kc][0], kh[kc][2]);
                MMA16816(sc[2*np+1], qfh[kc], kh[kc][1], kh[kc][3]);
                MMA16816(sc[2*np+1], qfh[kc], kl[kc][1], kl[kc][3]);
                MMA16816(sc[2*np+1], qfl[kc], kh[kc][1], kh[kc][3]);
            }
        }

        // ---- online softmax ----
        #pragma unroll
        for (int r = 0; r < 2; r++) {
            float mx = -1e30f;
            #pragma unroll
            for (int j = 0; j < 8; j++) {
                sc[j][2*r]   = sc[j][2*r]   * 0.125f + Ms[j * 8 + t2];
                sc[j][2*r+1] = sc[j][2*r+1] * 0.125f + Ms[j * 8 + t2 + 1];
                mx = fmaxf(mx, fmaxf(sc[j][2*r], sc[j][2*r+1]));
            }
            mx = fmaxf(mx, __shfl_xor_sync(0xffffffffu, mx, 1));
            mx = fmaxf(mx, __shfl_xor_sync(0xffffffffu, mx, 2));
            const float nm = fmaxf(mrow[r], mx);
            const float f  = __expf(mrow[r] - nm);
            mrow[r] = nm;
            float sum = 0.f;
            #pragma unroll
            for (int j = 0; j < 8; j++) {
                sc[j][2*r]   = __expf(sc[j][2*r]   - nm);
                sc[j][2*r+1] = __expf(sc[j][2*r+1] - nm);
                sum += sc[j][2*r] + sc[j][2*r+1];
            }
            sum += __shfl_xor_sync(0xffffffffu, sum, 1);
            sum += __shfl_xor_sync(0xffffffffu, sum, 2);
            lrow[r] = lrow[r] * f + sum;
            #pragma unroll
            for (int j = 0; j < 8; j++) {
                accO[j][2*r]   *= f;
                accO[j][2*r+1] *= f;
            }
        }

        // ---- O += P @ V ----
        #pragma unroll
        for (int kc = 0; kc < 4; kc++) {
            uint32_t pah[4], pal[4];
            pack_hl(sc[2*kc][0],   sc[2*kc][1],   pah[0], pal[0]);
            pack_hl(sc[2*kc][2],   sc[2*kc][3],   pah[1], pal[1]);
            pack_hl(sc[2*kc+1][0], sc[2*kc+1][1], pah[2], pal[2]);
            pack_hl(sc[2*kc+1][2], sc[2*kc+1][3], pah[3], pal[3]);
            #pragma unroll
            for (int nd = 0; nd < 4; nd++) {
                uint32_t vh[4], vl[4];
                const uint32_t vo = ((kc * 16 + lane16) * AQS + nd * 16 + lane8) * 2;
                LDSM_X4T(vh[0], vh[1], vh[2], vh[3], vsh + vo);
                LDSM_X4T(vl[0], vl[1], vl[2], vl[3], vsl + vo);
                MMA16816(accO[nd*2],   pah, vh[0], vh[1]);
                MMA16816(accO[nd*2],   pah, vl[0], vl[1]);
                MMA16816(accO[nd*2],   pal, vh[0], vh[1]);
                MMA16816(accO[nd*2+1], pah, vh[2], vh[3]);
                MMA16816(accO[nd*2+1], pah, vl[2], vl[3]);
                MMA16816(accO[nd*2+1], pal, vh[2], vh[3]);
            }
        }
    }

    // ---- epilogue: ctx hi/lo ----
    #pragma unroll
    for (int r = 0; r < 2; r++) {
        const float inv = 1.0f / lrow[r];
        const int qrow = q0 + wid * 16 + g + r * 8;
        const size_t base = ((size_t)(b * S_LEN + qrow)) * D_MODEL + h * DK + t2;
        #pragma unroll
        for (int j = 0; j < 8; j++) {
            uint32_t hw, lw;
            pack_hl(accO[j][2*r] * inv, accO[j][2*r+1] * inv, hw, lw);
            *(uint32_t*)(Oh + base + j * 8) = hw;
            *(uint32_t*)(Ol + base + j * 8) = lw;
        }
    }
}

// ---------------- launch ---------------------------------------------------
extern "C" void kernel_launch(void* const* d_in, const int* in_sizes, int n_in,
                              void* d_out, int out_size)
{
    const float* x   = (const float*)d_in[0];
    const int*   msk = (const int*)  d_in[1];
    const float* wq  = (const float*)d_in[2];
    const float* bq  = (const float*)d_in[3];
    const float* wk  = (const float*)d_in[4];
    const float* bk  = (const float*)d_in[5];
    const float* wv  = (const float*)d_in[6];
    const float* bv  = (const float*)d_in[7];
    const float* wo  = (const float*)d_in[8];
    const float* bo  = (const float*)d_in[9];
    const float* w1  = (const float*)d_in[10];
    const float* b1  = (const float*)d_in[11];
    const float* w2  = (const float*)d_in[12];
    const float* b2  = (const float*)d_in[13];
    const float* l1a = (const float*)d_in[14];
    const float* l1b = (const float*)d_in[15];
    const float* l2a = (const float*)d_in[16];
    const float* l2b = (const float*)d_in[17];
    float* out = (float*)d_out;

    bf16 *xnh, *xnl, *qh, *ql, *kh, *kl, *vh, *vl, *ctxh, *ctxl;
    bf16 *xn2h, *xn2l, *midh, *midl;
    bf16 *wqh, *wql, *wkh, *wkl, *wvh, *wvl, *woh, *wol, *w1h, *w1l, *w2h, *w2l;
    float* hbuf;
    cudaGetSymbolAddress((void**)&xnh,  g_xn_h);
    cudaGetSymbolAddress((void**)&xnl,  g_xn_l);
    cudaGetSymbolAddress((void**)&qh,   g_q_h);
    cudaGetSymbolAddress((void**)&ql,   g_q_l);
    cudaGetSymbolAddress((void**)&kh,   g_k_h);
    cudaGetSymbolAddress((void**)&kl,   g_k_l);
    cudaGetSymbolAddress((void**)&vh,   g_v_h);
    cudaGetSymbolAddress((void**)&vl,   g_v_l);
    cudaGetSymbolAddress((void**)&ctxh, g_ctx_h);
    cudaGetSymbolAddress((void**)&ctxl, g_ctx_l);
    cudaGetSymbolAddress((void**)&hbuf, g_hbuf);
    cudaGetSymbolAddress((void**)&xn2h, g_xn2_h);
    cudaGetSymbolAddress((void**)&xn2l, g_xn2_l);
    cudaGetSymbolAddress((void**)&midh, g_mid_h);
    cudaGetSymbolAddress((void**)&midl, g_mid_l);
    cudaGetSymbolAddress((void**)&wqh,  g_wq_h);
    cudaGetSymbolAddress((void**)&wql,  g_wq_l);
    cudaGetSymbolAddress((void**)&wkh,  g_wk_h);
    cudaGetSymbolAddress((void**)&wkl,  g_wk_l);
    cudaGetSymbolAddress((void**)&wvh,  g_wv_h);
    cudaGetSymbolAddress((void**)&wvl,  g_wv_l);
    cudaGetSymbolAddress((void**)&woh,  g_wo_h);
    cudaGetSymbolAddress((void**)&wol,  g_wo_l);
    cudaGetSymbolAddress((void**)&w1h,  g_w1_h);
    cudaGetSymbolAddress((void**)&w1l,  g_w1_l);
    cudaGetSymbolAddress((void**)&w2h,  g_w2_h);
    cudaGetSymbolAddress((void**)&w2l,  g_w2_l);

    cudaFuncSetAttribute((const void*)mma_gemm<false,false,true>,
        cudaFuncAttributeMaxDynamicSharedMemorySize, GEMM_SMEM);
    cudaFuncSetAttribute((const void*)mma_gemm<false,true,false>,
        cudaFuncAttributeMaxDynamicSharedMemorySize, GEMM_SMEM);
    cudaFuncSetAttribute((const void*)mma_gemm<true,false,true>,
        cudaFuncAttributeMaxDynamicSharedMemorySize, GEMM_SMEM);
    cudaFuncSetAttribute(attn_mma,
        cudaFuncAttributeMaxDynamicSharedMemorySize, ATTN_SMEM_B);

    // 0. pre-split weights (fp32 -> bf16 hi/lo)
    const int NW = D_MODEL * D_MODEL;      // 1M
    const int NF = D_MODEL * F_FFN;        // 4M
    split_kernel<<<NW / 1024, 256>>>(wq, wqh, wql);
    split_kernel<<<NW / 1024, 256>>>(wk, wkh, wkl);
    split_kernel<<<NW / 1024, 256>>>(wv, wvh, wvl);
    split_kernel<<<NW / 1024, 256>>>(wo, woh, wol);
    split_kernel<<<NF / 1024, 256>>>(w1, w1h, w1l);
    split_kernel<<<NF / 1024, 256>>>(w2, w2h, w2l);

    // 1. ln1 -> xn hi/lo
    ln_split_kernel<<<M_ROWS, 256>>>(x, l1a, l1b, xnh, xnl);
    // 2. QKV projections (bf16 out)
    mma_gemm<false,false,true><<<dim3(D_MODEL/128, M_ROWS/128), 256, GEMM_SMEM>>>(
        xnh, xnl, wqh, wql, bq, nullptr, nullptr, qh, ql, M_ROWS, D_MODEL, D_MODEL);
    mma_gemm<false,false,true><<<dim3(D_MODEL/128, M_ROWS/128), 256, GEMM_SMEM>>>(
        xnh, xnl, wkh, wkl, bk, nullptr, nullptr, kh, kl, M_ROWS, D_MODEL, D_MODEL);
    mma_gemm<false,false,true><<<dim3(D_MODEL/128, M_ROWS/128), 256, GEMM_SMEM>>>(
        xnh, xnl, wvh, wvl, bv, nullptr, nullptr, vh, vl, M_ROWS, D_MODEL, D_MODEL);
    // 3. attention -> ctx hi/lo
    attn_mma<<<dim3(S_LEN/128, N_HEADS, B_SZ), 256, ATTN_SMEM_B>>>(
        qh, ql, kh, kl, vh, vl, msk, ctxh, ctxl);
    // 4. output projection + residual(x) -> h (fp32)
    mma_gemm<false,true,false><<<dim3(D_MODEL/128, M_ROWS/128), 256, GEMM_SMEM>>>(
        ctxh, ctxl, woh, wol, bo, x, hbuf, nullptr, nullptr, M_ROWS, D_MODEL, D_MODEL);
    // 5. ln2 -> xn2 hi/lo
    ln_split_kernel<<<M_ROWS, 256>>>(hbuf, l2a, l2b, xn2h, xn2l);
    // 6. FFN up + relu (bf16 out)
    mma_gemm<true,false,true><<<dim3(F_FFN/128, M_ROWS/128), 256, GEMM_SMEM>>>(
        xn2h, xn2l, w1h, w1l, b1, nullptr, nullptr, midh, midl, M_ROWS, F_FFN, D_MODEL);
    // 7. FFN down + residual(h) -> out (fp32)
    mma_gemm<false,true,false><<<dim3(D_MODEL/128, M_ROWS/128), 256, GEMM_SMEM>>>(
        midh, midl, w2h, w2l, b2, hbuf, out, nullptr, nullptr, M_ROWS, D_MODEL, F_FFN);
}